// round 15
// baseline (speedup 1.0000x reference)
#include <cuda_runtime.h>
#include <cuda_fp16.h>
#include <cstdint>

// ---------------- sizes ----------------
#define BATCH 256
#define NY 3686400              // 256*64*15*15
#define H1N (256*64*62*62)
#define H2N (256*64*31*31)

// smem layout for ODE mma conv (R11-proven)
#define MM_HHI 0                // halo A (fp16): 306 rows x 128B
#define MM_BHI 39168            // weights (fp16): 64 rows x 128B
#define MM_STAT 47360           // sums/sumsq/scv/shv: 4 x 64 floats
#define MM_SMEM_BYTES 48384

// smem layout for downsample 4x4/s2 mma conv
#define C4_W 78336              // halo: 612 rows x 128B, then weights 8192B
#define C4_SMEM_BYTES 86528

// ---------------- scratch (device globals, no allocation) ----------------
__device__ float g_h1[H1N];
__device__ float g_h2[H2N];
__device__ float g_y[NY];
__device__ float g_t0[NY];
__device__ float g_t1[NY];
__device__ float g_k[6][NY];
__device__ float g_S1[64 * 225];
__device__ float g_S2[64 * 225];
__device__ float g_pool[256 * 64];
__device__ __half g_w1[9 * 4096];
__device__ __half g_w2[9 * 4096];
__device__ __half g_w4a[16 * 4096];
__device__ __half g_w4b[16 * 4096];

// ---------------- helpers ----------------
__inline__ __device__ float warpSum(float v) {
#pragma unroll
    for (int o = 16; o; o >>= 1) v += __shfl_xor_sync(0xffffffffu, v, o);
    return v;
}
__device__ __forceinline__ uint32_t smem_u32(const void* p) {
    uint32_t a;
    asm("{ .reg .u64 tmp; cvta.to.shared.u64 tmp, %1; cvt.u32.u64 %0, tmp; }"
        : "=r"(a) : "l"(p));
    return a;
}
__device__ __forceinline__ void ldsm4(uint32_t* r, uint32_t addr) {
    asm volatile("ldmatrix.sync.aligned.m8n8.x4.shared.b16 {%0,%1,%2,%3}, [%4];"
        : "=r"(r[0]), "=r"(r[1]), "=r"(r[2]), "=r"(r[3]) : "r"(addr));
}
__device__ __forceinline__ void ldsm2(uint32_t* r, uint32_t addr) {
    asm volatile("ldmatrix.sync.aligned.m8n8.x2.shared.b16 {%0,%1}, [%2];"
        : "=r"(r[0]), "=r"(r[1]) : "r"(addr));
}
__device__ __forceinline__ void mma_fp16(float* c, const uint32_t* a, const uint32_t* b) {
    asm volatile("mma.sync.aligned.m16n8k16.row.col.f32.f16.f16.f32 "
        "{%0,%1,%2,%3}, {%4,%5,%6,%7}, {%8,%9}, {%0,%1,%2,%3};"
        : "+f"(c[0]), "+f"(c[1]), "+f"(c[2]), "+f"(c[3])
        : "r"(a[0]), "r"(a[1]), "r"(a[2]), "r"(a[3]), "r"(b[0]), "r"(b[1]));
}

// shared conv body: tap loop + GN epilogue (input halo already filled & normalized)
__device__ __forceinline__ void conv_body_gn(
    char* smem, uint32_t HHIa, uint32_t BHIa,
    const __half* __restrict__ wq,
    const float* __restrict__ bias, const float* __restrict__ S, float t,
    const float* __restrict__ gamma, const float* __restrict__ beta, int relu,
    float* __restrict__ outp, size_t base, int tid, int wid, int lane)
{
    float* sums  = (float*)(smem + MM_STAT);
    float* sumsq = sums + 64;
    float* scv   = sums + 128;
    float* shv   = sums + 192;

    float acc[2][8][4];
#pragma unroll
    for (int m = 0; m < 2; m++)
#pragma unroll
        for (int n = 0; n < 8; n++)
#pragma unroll
            for (int v = 0; v < 4; v++) acc[m][n][v] = 0.f;

    for (int tap = 0; tap < 9; tap++) {
        __syncthreads();
        {
            const uint4* gh = (const uint4*)(wq + tap * 4096);
            uint4* sh = (uint4*)(smem + MM_BHI);
            for (int i = tid; i < 512; i += 256) sh[i] = gh[i];
        }
        __syncthreads();

        int dd = (tap / 3) * 18 + (tap % 3);
        for (int kt = 0; kt < 4; kt++) {
            uint32_t bh[8][2];
            int nrow = lane & 7;
            int bphys = ((kt * 2 + ((lane >> 3) & 1)) ^ nrow) * 16;
#pragma unroll
            for (int nt = 0; nt < 8; nt++)
                ldsm2(bh[nt], BHIa + (nt * 8 + nrow) * 128 + bphys);
#pragma unroll
            for (int mti = 0; mti < 2; mti++) {
                int mtile = wid + mti * 8;
                if (mtile < 15) {
                    int r = mtile * 18 + (lane & 15) + dd;
                    int aphys = ((kt * 2 + (lane >> 4)) ^ (r & 7)) * 16;
                    uint32_t ah[4];
                    ldsm4(ah, HHIa + r * 128 + aphys);
#pragma unroll
                    for (int nt = 0; nt < 8; nt++)
                        mma_fp16(acc[mti][nt], ah, bh[nt]);
                }
            }
        }
    }

    int row0 = lane >> 2;
    int colb = (lane & 3) * 2;
    bool v1ok = (row0 + 8) < 15;

#pragma unroll
    for (int mti = 0; mti < 2; mti++) {
        int mtile = wid + mti * 8;
        if (mtile >= 15) continue;
        int p0 = mtile * 15 + row0, p1 = p0 + 8;
#pragma unroll
        for (int nt = 0; nt < 8; nt++) {
            int co = nt * 8 + colb;
            float bv0 = __ldg(&bias[co]), bv1 = __ldg(&bias[co + 1]);
            acc[mti][nt][0] += bv0 + t * __ldg(&S[co * 225 + p0]);
            acc[mti][nt][1] += bv1 + t * __ldg(&S[(co + 1) * 225 + p0]);
            if (v1ok) {
                acc[mti][nt][2] += bv0 + t * __ldg(&S[co * 225 + p1]);
                acc[mti][nt][3] += bv1 + t * __ldg(&S[(co + 1) * 225 + p1]);
            }
        }
    }

    if (tid < 64) { sums[tid] = 0.f; sumsq[tid] = 0.f; }
    __syncthreads();
#pragma unroll
    for (int nt = 0; nt < 8; nt++) {
        float sa = 0.f, s2a = 0.f, sb = 0.f, s2b = 0.f;
#pragma unroll
        for (int mti = 0; mti < 2; mti++) {
            int mtile = wid + mti * 8;
            if (mtile >= 15) continue;
            float v0 = acc[mti][nt][0], v1 = acc[mti][nt][1];
            sa += v0; s2a = fmaf(v0, v0, s2a);
            sb += v1; s2b = fmaf(v1, v1, s2b);
            if (v1ok) {
                float v2 = acc[mti][nt][2], v3 = acc[mti][nt][3];
                sa += v2; s2a = fmaf(v2, v2, s2a);
                sb += v3; s2b = fmaf(v3, v3, s2b);
            }
        }
#pragma unroll
        for (int o = 4; o <= 16; o <<= 1) {
            sa  += __shfl_xor_sync(0xffffffffu, sa, o);
            s2a += __shfl_xor_sync(0xffffffffu, s2a, o);
            sb  += __shfl_xor_sync(0xffffffffu, sb, o);
            s2b += __shfl_xor_sync(0xffffffffu, s2b, o);
        }
        if (lane < 4) {
            int co = nt * 8 + lane * 2;
            atomicAdd(&sums[co], sa);  atomicAdd(&sumsq[co], s2a);
            atomicAdd(&sums[co + 1], sb); atomicAdd(&sumsq[co + 1], s2b);
        }
    }
    __syncthreads();
    if (tid < 32) {
        int ca = 2 * tid, cb = ca + 1;
        float mu = (sums[ca] + sums[cb]) * (1.f / 450.f);
        float var = (sumsq[ca] + sumsq[cb]) * (1.f / 450.f) - mu * mu;
        float inv = rsqrtf(var + 1e-5f);
        float sa = inv * gamma[ca], sb2 = inv * gamma[cb];
        scv[ca] = sa; shv[ca] = beta[ca] - mu * sa;
        scv[cb] = sb2; shv[cb] = beta[cb] - mu * sb2;
    }
    __syncthreads();

#pragma unroll
    for (int mti = 0; mti < 2; mti++) {
        int mtile = wid + mti * 8;
        if (mtile >= 15) continue;
        int p0 = mtile * 15 + row0, p1 = p0 + 8;
#pragma unroll
        for (int nt = 0; nt < 8; nt++) {
            int co = nt * 8 + colb;
            float sc0 = scv[co], sh0 = shv[co];
            float sc1 = scv[co + 1], sh1 = shv[co + 1];
            float* oc0 = outp + base + (size_t)co * 225;
            float* oc1 = oc0 + 225;
            float r0 = fmaf(acc[mti][nt][0], sc0, sh0);
            float r1 = fmaf(acc[mti][nt][1], sc1, sh1);
            if (relu) { r0 = fmaxf(r0, 0.f); r1 = fmaxf(r1, 0.f); }
            oc0[p0] = r0; oc1[p0] = r1;
            if (v1ok) {
                float r2 = fmaf(acc[mti][nt][2], sc0, sh0);
                float r3 = fmaf(acc[mti][nt][3], sc1, sh1);
                if (relu) { r2 = fmaxf(r2, 0.f); r3 = fmaxf(r3, 0.f); }
                oc0[p1] = r2; oc1[p1] = r3;
            }
        }
    }
}

// ---------------- conv1: 1->64, 3x3, valid ----------------
__global__ void conv1_kernel(const float* __restrict__ x, float* __restrict__ out,
                             const float* __restrict__ w, const float* __restrict__ bias)
{
    __shared__ float sx[18][18];
    __shared__ float swt[64 * 9];
    __shared__ float sb[64];
    int b = blockIdx.y;
    int tileX = blockIdx.x & 3, tileY = blockIdx.x >> 2;
    int tx = threadIdx.x, ty = threadIdx.y;
    int tid = ty * 16 + tx;

    for (int s = tid; s < 576; s += 256) swt[s] = w[s];
    if (tid < 64) sb[tid] = bias[tid];

    const float* xb = x + (size_t)b * 64 * 64;
    int ox0 = tileX * 16, oy0 = tileY * 16;
    for (int s = tid; s < 18 * 18; s += 256) {
        int r = s / 18, c = s % 18;
        int iy = oy0 + r, ix = ox0 + c;
        sx[r][c] = (iy < 64 && ix < 64) ? xb[iy * 64 + ix] : 0.f;
    }
    __syncthreads();

    int ox = ox0 + tx, oy = oy0 + ty;
    if (ox >= 62 || oy >= 62) return;

    float v[9];
#pragma unroll
    for (int ky = 0; ky < 3; ky++)
#pragma unroll
        for (int kx = 0; kx < 3; kx++)
            v[ky * 3 + kx] = sx[ty + ky][tx + kx];

    float* ob = out + (size_t)b * 64 * 3844 + oy * 62 + ox;
#pragma unroll 4
    for (int co = 0; co < 64; co++) {
        float a = sb[co];
#pragma unroll
        for (int k = 0; k < 9; k++) a = fmaf(swt[co * 9 + k], v[k], a);
        ob[(size_t)co * 3844] = a;
    }
}

// ---------------- generic GroupNorm (big HW) ----------------
__global__ void gn_big_kernel(const float* __restrict__ in, float* __restrict__ out,
                              const float* __restrict__ gamma, const float* __restrict__ beta,
                              int HW, int relu)
{
    __shared__ float rs[8], rs2[8], stats[2];
    int bg = blockIdx.x;
    int c0 = (bg & 31) * 2;
    size_t base = (size_t)bg * 2 * HW;
    int n = 2 * HW;
    float s = 0.f, s2 = 0.f;
    for (int i = threadIdx.x; i < n; i += 256) {
        float v = in[base + i];
        s += v; s2 = fmaf(v, v, s2);
    }
    s = warpSum(s); s2 = warpSum(s2);
    int wi = threadIdx.x >> 5, lane = threadIdx.x & 31;
    if (lane == 0) { rs[wi] = s; rs2[wi] = s2; }
    __syncthreads();
    if (threadIdx.x == 0) {
        float a = 0.f, bb = 0.f;
#pragma unroll
        for (int i = 0; i < 8; i++) { a += rs[i]; bb += rs2[i]; }
        float mu = a / (float)n;
        stats[0] = mu;
        stats[1] = rsqrtf(bb / (float)n - mu * mu + 1e-5f);
    }
    __syncthreads();
    float mu = stats[0], inv = stats[1];
    float sc0 = inv * gamma[c0],     sh0 = beta[c0]     - mu * sc0;
    float sc1 = inv * gamma[c0 + 1], sh1 = beta[c0 + 1] - mu * sc1;
    for (int i = threadIdx.x; i < n; i += 256) {
        float v = in[base + i];
        float r = (i < HW) ? fmaf(v, sc0, sh0) : fmaf(v, sc1, sh1);
        if (relu) r = fmaxf(r, 0.f);
        out[base + i] = r;
    }
}

// ---------------- GroupNorm 15x15: 8 groups per 256-thr block (head only) ----------------
__global__ void gn8_kernel(const float* __restrict__ in, float* __restrict__ out,
                           const float* __restrict__ gamma, const float* __restrict__ beta,
                           int relu)
{
    int wid = threadIdx.x >> 5, lane = threadIdx.x & 31;
    int bg = blockIdx.x * 8 + wid;
    size_t base = (size_t)bg * 450;
    int c0 = (bg & 31) * 2;
    float v[15];
    float s = 0.f, s2 = 0.f;
#pragma unroll
    for (int k = 0; k < 15; k++) {
        int i = k * 32 + lane;
        float xv = (i < 450) ? in[base + i] : 0.f;
        v[k] = xv;
        s += xv; s2 = fmaf(xv, xv, s2);
    }
    s = warpSum(s); s2 = warpSum(s2);
    float mu = s * (1.f / 450.f);
    float inv = rsqrtf(s2 * (1.f / 450.f) - mu * mu + 1e-5f);
    float sc0 = inv * gamma[c0],     sh0 = beta[c0]     - mu * sc0;
    float sc1 = inv * gamma[c0 + 1], sh1 = beta[c0 + 1] - mu * sc1;
#pragma unroll
    for (int k = 0; k < 15; k++) {
        int i = k * 32 + lane;
        if (i < 450) {
            float r = (i < 225) ? fmaf(v[k], sc0, sh0) : fmaf(v[k], sc1, sh1);
            if (relu) r = fmaxf(r, 0.f);
            out[base + i] = r;
        }
    }
}

// ---------------- precompute S[co][p] ----------------
__global__ void precomp_s_kernel(const float* __restrict__ w, float* __restrict__ S)
{
    int co = blockIdx.x;
    int p = threadIdx.x;
    int y = p / 15, x = p % 15;
    float a = 0.f;
#pragma unroll
    for (int ky = 0; ky < 3; ky++) {
        int iy = y - 1 + ky;
        if ((unsigned)iy < 15u) {
#pragma unroll
            for (int kx = 0; kx < 3; kx++) {
                int ix = x - 1 + kx;
                if ((unsigned)ix < 15u) a += w[(size_t)co * 65 * 9 + ky * 3 + kx];
            }
        }
    }
    S[co * 225 + p] = a;
}

// ---------------- precompute swizzled fp16 weights per tap (3x3 ODE convs) ----------------
__global__ void precomp_w_kernel(const float* __restrict__ w, __half* __restrict__ hi)
{
    int tap = blockIdx.x;
    for (int s = threadIdx.x; s < 4096; s += 256) {
        int co = s >> 6, ci = s & 63;
        float v = w[((size_t)co * 65 + ci + 1) * 9 + tap];
        int pos = tap * 4096 + co * 64 + ((((ci >> 3) ^ (co & 7)) << 3) + (ci & 7));
        hi[pos] = __float2half(v);
    }
}

// ---------------- precompute swizzled fp16 weights per tap (4x4 downsample convs) ----------------
__global__ void precomp_w4_kernel(const float* __restrict__ w, __half* __restrict__ hi)
{
    int tap = blockIdx.x;
    for (int s = threadIdx.x; s < 4096; s += 256) {
        int co = s >> 6, ci = s & 63;
        float v = w[(((size_t)co * 64) + ci) * 16 + tap];
        int pos = tap * 4096 + co * 64 + ((((ci >> 3) ^ (co & 7)) << 3) + (ci & 7));
        hi[pos] = __float2half(v);
    }
}

// ---------------- downsample conv 4x4 stride2 pad1 via fp16 mma ----------------
__global__ void __launch_bounds__(256, 2)
conv4_mma(const float* __restrict__ in, float* __restrict__ out,
          const __half* __restrict__ wq, const float* __restrict__ bias,
          int Hin, int Hout)
{
    extern __shared__ __align__(128) char smem[];
    uint32_t smBase = smem_u32(smem);
    const uint32_t HA = smBase;
    const uint32_t BA = smBase + C4_W;

    int tid = threadIdx.x;
    int wid = tid >> 5, lane = tid & 31;
    int b = blockIdx.z;
    int ox0 = blockIdx.x * 16, oy0 = blockIdx.y * 8;
    int iy0 = 2 * oy0 - 1, ix0 = 2 * ox0 - 1;

    {
        uint4 z = make_uint4(0u, 0u, 0u, 0u);
        uint4* h4 = (uint4*)smem;
        for (int i = tid; i < 4896; i += 256) h4[i] = z;
    }
    __syncthreads();
    {
        __half* hh = (__half*)smem;
        const float* inb = in + ((size_t)b * 64) * Hin * Hin;
        for (int s = tid; s < 64 * 612; s += 256) {
            int ci = s / 612, rr = s % 612;
            int ly = rr / 34, lx = rr % 34;
            int iy = iy0 + ly, ix = ix0 + lx;
            if ((unsigned)iy < (unsigned)Hin && (unsigned)ix < (unsigned)Hin) {
                float v = inb[(size_t)ci * Hin * Hin + iy * Hin + ix];
                int off = rr * 64 + ((((ci >> 3) ^ (rr & 7)) << 3) + (ci & 7));
                hh[off] = __float2half(v);
            }
        }
    }

    float acc[8][4];
#pragma unroll
    for (int n = 0; n < 8; n++)
#pragma unroll
        for (int v = 0; v < 4; v++) acc[n][v] = 0.f;

    for (int tap = 0; tap < 16; tap++) {
        __syncthreads();
        {
            const uint4* gh = (const uint4*)(wq + tap * 4096);
            uint4* sh = (uint4*)(smem + C4_W);
            for (int i = tid; i < 512; i += 256) sh[i] = gh[i];
        }
        __syncthreads();

        int ky = tap >> 2, kx = tap & 3;
        for (int kt = 0; kt < 4; kt++) {
            uint32_t bh[8][2];
            int nrow = lane & 7;
            int bphys = ((kt * 2 + ((lane >> 3) & 1)) ^ nrow) * 16;
#pragma unroll
            for (int nt = 0; nt < 8; nt++)
                ldsm2(bh[nt], BA + (nt * 8 + nrow) * 128 + bphys);

            int r = (2 * wid + ky) * 34 + 2 * (lane & 15) + kx;
            int aphys = ((kt * 2 + (lane >> 4)) ^ (r & 7)) * 16;
            uint32_t ah[4];
            ldsm4(ah, HA + r * 128 + aphys);
#pragma unroll
            for (int nt = 0; nt < 8; nt++)
                mma_fp16(acc[nt], ah, bh[nt]);
        }
    }

    int oy = oy0 + wid;
    if (oy < Hout) {
        int row0 = lane >> 2;
        int colb = (lane & 3) * 2;
        int oxa = ox0 + row0, oxb = ox0 + row0 + 8;
        int HW = Hout * Hout;
        float* ob = out + ((size_t)b * 64) * HW + oy * Hout;
#pragma unroll
        for (int nt = 0; nt < 8; nt++) {
            int co = nt * 8 + colb;
            float bv0 = __ldg(&bias[co]), bv1 = __ldg(&bias[co + 1]);
            if (oxa < Hout) {
                ob[(size_t)co * HW + oxa] = acc[nt][0] + bv0;
                ob[(size_t)(co + 1) * HW + oxa] = acc[nt][1] + bv1;
            }
            if (oxb < Hout) {
                ob[(size_t)co * HW + oxb] = acc[nt][2] + bv0;
                ob[(size_t)(co + 1) * HW + oxb] = acc[nt][3] + bv1;
            }
        }
    }
}

// ---------------- feval conv1: fused combine + GN1 + relu prologue, conv, GN2 epilogue ----------------
__global__ void __launch_bounds__(256, 2)
ode_conv1_gn(float* __restrict__ y,
             const float* __restrict__ k0, const float* __restrict__ k1,
             const float* __restrict__ k2, const float* __restrict__ k3,
             const float* __restrict__ k4,
             float c0, float c1, float c2, float c3, float c4, int nk, int writeY,
             const float* __restrict__ g1, const float* __restrict__ bb1,
             const __half* __restrict__ wq,
             const float* __restrict__ bias, const float* __restrict__ S, float t,
             const float* __restrict__ gamma, const float* __restrict__ beta,
             float* __restrict__ outp)
{
    extern __shared__ __align__(128) char smem[];
    uint32_t smBase = smem_u32(smem);
    float* sums  = (float*)(smem + MM_STAT);
    float* sumsq = sums + 64;
    float* scv   = sums + 128;
    float* shv   = sums + 192;

    int tid = threadIdx.x;
    int wid = tid >> 5, lane = tid & 31;
    int b = blockIdx.x;
    size_t base = (size_t)b * 14400;
    __half* hh = (__half*)smem;

    // zero halo
    {
        uint4 z = make_uint4(0u, 0u, 0u, 0u);
        uint4* h4 = (uint4*)smem;
        for (int i = tid; i < 2448; i += 256) h4[i] = z;
    }
    __syncthreads();

    // combine + GN1 stats; write raw fp16 halo. ch = tid>>2, q = tid&3
    int ch = tid >> 2, q = tid & 3;
    {
        float s = 0.f, s2 = 0.f;
        for (int j = q; j < 225; j += 4) {
            size_t idx = base + ch * 225 + j;
            float v = y[idx];
            if (nk > 0) v = fmaf(c0, k0[idx], v);
            if (nk > 1) v = fmaf(c1, k1[idx], v);
            if (nk > 2) v = fmaf(c2, k2[idx], v);
            if (nk > 3) v = fmaf(c3, k3[idx], v);
            if (nk > 4) v = fmaf(c4, k4[idx], v);
            if (writeY) y[idx] = v;
            s += v; s2 = fmaf(v, v, s2);
            int r = (j / 15 + 1) * 18 + (j % 15) + 1;
            hh[r * 64 + ((((ch >> 3) ^ (r & 7)) << 3) + (ch & 7))] = __float2half(v);
        }
        s  += __shfl_xor_sync(0xffffffffu, s, 1);
        s  += __shfl_xor_sync(0xffffffffu, s, 2);
        s2 += __shfl_xor_sync(0xffffffffu, s2, 1);
        s2 += __shfl_xor_sync(0xffffffffu, s2, 2);
        if (q == 0) { sums[ch] = s; sumsq[ch] = s2; }
    }
    __syncthreads();
    if (tid < 32) {
        int ca = 2 * tid, cb = ca + 1;
        float mu = (sums[ca] + sums[cb]) * (1.f / 450.f);
        float var = (sumsq[ca] + sumsq[cb]) * (1.f / 450.f) - mu * mu;
        float inv = rsqrtf(var + 1e-5f);
        float sa = inv * g1[ca], sb2 = inv * g1[cb];
        scv[ca] = sa; shv[ca] = bb1[ca] - mu * sa;
        scv[cb] = sb2; shv[cb] = bb1[cb] - mu * sb2;
    }
    __syncthreads();
    // normalize + relu halo in place
    {
        float sc = scv[ch], sh = shv[ch];
        for (int j = q; j < 225; j += 4) {
            int r = (j / 15 + 1) * 18 + (j % 15) + 1;
            int off = r * 64 + ((((ch >> 3) ^ (r & 7)) << 3) + (ch & 7));
            float v = __half2float(hh[off]);
            hh[off] = __float2half(fmaxf(fmaf(v, sc, sh), 0.f));
        }
    }
    // conv body's leading sync orders the normalize writes

    conv_body_gn(smem, smBase + MM_HHI, smBase + MM_BHI, wq, bias, S, t,
                 gamma, beta, 1, outp, base, tid, wid, lane);
}

// ---------------- feval conv2: plain fill prologue, conv, GN3 epilogue ----------------
__global__ void __launch_bounds__(256, 2)
ode_conv_gn(const float* __restrict__ in, float* __restrict__ out,
            const __half* __restrict__ wq,
            const float* __restrict__ bias, const float* __restrict__ S, float t,
            const float* __restrict__ gamma, const float* __restrict__ beta, int relu)
{
    extern __shared__ __align__(128) char smem[];
    uint32_t smBase = smem_u32(smem);

    int tid = threadIdx.x;
    int wid = tid >> 5, lane = tid & 31;
    int b = blockIdx.x;
    size_t base = (size_t)b * 14400;

    {
        uint4 z = make_uint4(0u, 0u, 0u, 0u);
        uint4* h4 = (uint4*)smem;
        for (int i = tid; i < 2448; i += 256) h4[i] = z;
    }
    __syncthreads();
    {
        __half* hh = (__half*)smem;
        for (int s = tid; s < 14400; s += 256) {
            int ci = s / 225, p = s % 225;
            float v = in[base + s];
            int r = (p / 15 + 1) * 18 + (p % 15) + 1;
            hh[r * 64 + ((((ci >> 3) ^ (r & 7)) << 3) + (ci & 7))] = __float2half(v);
        }
    }

    conv_body_gn(smem, smBase + MM_HHI, smBase + MM_BHI, wq, bias, S, t,
                 gamma, beta, relu, out, base, tid, wid, lane);
}

// ---------------- final combine ----------------
__global__ void combine_kernel(const float4* __restrict__ y, float4* __restrict__ dst,
                               const float4* __restrict__ p0, const float4* __restrict__ p1,
                               const float4* __restrict__ p2, const float4* __restrict__ p3,
                               const float4* __restrict__ p4,
                               float c0, float c1, float c2, float c3, float c4)
{
    int i = blockIdx.x * 256 + threadIdx.x;
    float4 a = y[i];
    float4 t;
    t = p0[i]; a.x = fmaf(c0, t.x, a.x); a.y = fmaf(c0, t.y, a.y); a.z = fmaf(c0, t.z, a.z); a.w = fmaf(c0, t.w, a.w);
    t = p1[i]; a.x = fmaf(c1, t.x, a.x); a.y = fmaf(c1, t.y, a.y); a.z = fmaf(c1, t.z, a.z); a.w = fmaf(c1, t.w, a.w);
    t = p2[i]; a.x = fmaf(c2, t.x, a.x); a.y = fmaf(c2, t.y, a.y); a.z = fmaf(c2, t.z, a.z); a.w = fmaf(c2, t.w, a.w);
    t = p3[i]; a.x = fmaf(c3, t.x, a.x); a.y = fmaf(c3, t.y, a.y); a.z = fmaf(c3, t.z, a.z); a.w = fmaf(c3, t.w, a.w);
    t = p4[i]; a.x = fmaf(c4, t.x, a.x); a.y = fmaf(c4, t.y, a.y); a.z = fmaf(c4, t.z, a.z); a.w = fmaf(c4, t.w, a.w);
    dst[i] = a;
}

// ---------------- global mean pool ----------------
__global__ void pool_kernel(const float* __restrict__ in, float* __restrict__ out)
{
    int gw = (blockIdx.x * 256 + threadIdx.x) >> 5;
    int lane = threadIdx.x & 31;
    const float* p = in + (size_t)gw * 225;
    float s = 0.f;
    for (int i = lane; i < 225; i += 32) s += p[i];
    s = warpSum(s);
    if (lane == 0) out[gw] = s * (1.f / 225.f);
}

// ---------------- FC 64->10 ----------------
__global__ void fc_kernel(const float* __restrict__ pool, const float* __restrict__ w,
                          const float* __restrict__ bias, float* __restrict__ out)
{
    __shared__ float sp[64];
    int b = blockIdx.x;
    sp[threadIdx.x] = pool[b * 64 + threadIdx.x];
    __syncthreads();
    if (threadIdx.x < 10) {
        float a = bias[threadIdx.x];
#pragma unroll
        for (int c = 0; c < 64; c++) a = fmaf(sp[c], __ldg(&w[threadIdx.x * 64 + c]), a);
        out[b * 10 + threadIdx.x] = a;
    }
}

// ---------------- launch ----------------
extern "C" void kernel_launch(void* const* d_in, const int* in_sizes, int n_in,
                              void* d_out, int out_size)
{
    const float* x        = (const float*)d_in[0];
    const float* conv1_w  = (const float*)d_in[1];
    const float* conv1_b  = (const float*)d_in[2];
    const float* gn1_g    = (const float*)d_in[3];
    const float* gn1_b    = (const float*)d_in[4];
    const float* conv2_w  = (const float*)d_in[5];
    const float* conv2_b  = (const float*)d_in[6];
    const float* gn2_g    = (const float*)d_in[7];
    const float* gn2_b    = (const float*)d_in[8];
    const float* conv3_w  = (const float*)d_in[9];
    const float* conv3_b  = (const float*)d_in[10];
    const float* f_gn1_g  = (const float*)d_in[11];
    const float* f_gn1_b  = (const float*)d_in[12];
    const float* f_conv1_w= (const float*)d_in[13];
    const float* f_conv1_b= (const float*)d_in[14];
    const float* f_gn2_g  = (const float*)d_in[15];
    const float* f_gn2_b  = (const float*)d_in[16];
    const float* f_conv2_w= (const float*)d_in[17];
    const float* f_conv2_b= (const float*)d_in[18];
    const float* f_gn3_g  = (const float*)d_in[19];
    const float* f_gn3_b  = (const float*)d_in[20];
    const float* out_gn_g = (const float*)d_in[21];
    const float* out_gn_b = (const float*)d_in[22];
    const float* fc_w     = (const float*)d_in[23];
    const float* fc_b     = (const float*)d_in[24];
    float* out = (float*)d_out;

    float *h1, *h2, *y, *t0b, *t1b, *kbase, *S1, *S2, *pool;
    __half *w1q, *w2q, *w4a, *w4b;
    cudaGetSymbolAddress((void**)&h1, g_h1);
    cudaGetSymbolAddress((void**)&h2, g_h2);
    cudaGetSymbolAddress((void**)&y, g_y);
    cudaGetSymbolAddress((void**)&t0b, g_t0);
    cudaGetSymbolAddress((void**)&t1b, g_t1);
    cudaGetSymbolAddress((void**)&kbase, g_k);
    cudaGetSymbolAddress((void**)&S1, g_S1);
    cudaGetSymbolAddress((void**)&S2, g_S2);
    cudaGetSymbolAddress((void**)&pool, g_pool);
    cudaGetSymbolAddress((void**)&w1q, g_w1);
    cudaGetSymbolAddress((void**)&w2q, g_w2);
    cudaGetSymbolAddress((void**)&w4a, g_w4a);
    cudaGetSymbolAddress((void**)&w4b, g_w4b);
    float* kk[6];
    for (int i = 0; i < 6; i++) kk[i] = kbase + (size_t)i * NY;

    cudaFuncSetAttribute(ode_conv_gn, cudaFuncAttributeMaxDynamicSharedMemorySize, MM_SMEM_BYTES);
    cudaFuncSetAttribute(ode_conv1_gn, cudaFuncAttributeMaxDynamicSharedMemorySize, MM_SMEM_BYTES);
    cudaFuncSetAttribute(conv4_mma, cudaFuncAttributeMaxDynamicSharedMemorySize, C4_SMEM_BYTES);

    // ---- downsampling ----
    conv1_kernel<<<dim3(16, BATCH), dim3(16, 16)>>>(x, h1, conv1_w, conv1_b);
    gn_big_kernel<<<BATCH * 32, 256>>>(h1, h1, gn1_g, gn1_b, 62 * 62, 1);
    precomp_w4_kernel<<<16, 256>>>(conv2_w, w4a);
    precomp_w4_kernel<<<16, 256>>>(conv3_w, w4b);
    conv4_mma<<<dim3(2, 4, BATCH), 256, C4_SMEM_BYTES>>>(h1, h2, w4a, conv2_b, 62, 31);
    gn_big_kernel<<<BATCH * 32, 256>>>(h2, h2, gn2_g, gn2_b, 31 * 31, 1);
    conv4_mma<<<dim3(1, 2, BATCH), 256, C4_SMEM_BYTES>>>(h2, y, w4b, conv3_b, 31, 15);

    precomp_s_kernel<<<64, 225>>>(f_conv1_w, S1);
    precomp_s_kernel<<<64, 225>>>(f_conv2_w, S2);
    precomp_w_kernel<<<9, 256>>>(f_conv1_w, w1q);
    precomp_w_kernel<<<9, 256>>>(f_conv2_w, w2q);

    // feval: [combine+GN1+conv1+GN2] -> [conv2+GN3] -> k
    auto fev = [&](float t, const float* p0, const float* p1, const float* p2,
                   const float* p3, const float* p4,
                   double c0, double c1, double c2, double c3, double c4,
                   int nk, int writeY, float* kout) {
        ode_conv1_gn<<<BATCH, 256, MM_SMEM_BYTES>>>(
            y, p0 ? p0 : y, p1 ? p1 : y, p2 ? p2 : y, p3 ? p3 : y, p4 ? p4 : y,
            (float)c0, (float)c1, (float)c2, (float)c3, (float)c4, nk, writeY,
            f_gn1_g, f_gn1_b, w1q, f_conv1_b, S1, t, f_gn2_g, f_gn2_b, t1b);
        ode_conv_gn<<<BATCH, 256, MM_SMEM_BYTES>>>(t1b, kout, w2q, f_conv2_b, S2, t,
                                                   f_gn3_g, f_gn3_b, 0);
    };

    const double hs = 1.0 / 8.0;
    const double bf0 = hs * (35.0 / 384.0),  bf2 = hs * (500.0 / 1113.0);
    const double bf3 = hs * (125.0 / 192.0), bf4 = hs * (-2187.0 / 6784.0);
    const double bf5 = hs * (11.0 / 84.0);

    for (int st = 0; st < 8; st++) {
        double T0 = st * hs;
        if (st == 0)
            fev((float)T0, 0, 0, 0, 0, 0, 0, 0, 0, 0, 0, 0, 0, kk[0]);
        else
            fev((float)T0, kk[0], kk[2], kk[3], kk[4], kk[5],
                bf0, bf2, bf3, bf4, bf5, 5, 1, kk[0]);
        fev((float)(T0 + hs / 5.0), kk[0], 0, 0, 0, 0,
            hs * (1.0 / 5.0), 0, 0, 0, 0, 1, 0, kk[1]);
        fev((float)(T0 + 0.3 * hs), kk[0], kk[1], 0, 0, 0,
            hs * (3.0 / 40.0), hs * (9.0 / 40.0), 0, 0, 0, 2, 0, kk[2]);
        fev((float)(T0 + 0.8 * hs), kk[0], kk[1], kk[2], 0, 0,
            hs * (44.0 / 45.0), hs * (-56.0 / 15.0), hs * (32.0 / 9.0), 0, 0, 3, 0, kk[3]);
        fev((float)(T0 + (8.0 / 9.0) * hs), kk[0], kk[1], kk[2], kk[3], 0,
            hs * (19372.0 / 6561.0), hs * (-25360.0 / 2187.0),
            hs * (64448.0 / 6561.0), hs * (-212.0 / 729.0), 0, 4, 0, kk[4]);
        fev((float)(T0 + hs), kk[0], kk[1], kk[2], kk[3], kk[4],
            hs * (9017.0 / 3168.0), hs * (-355.0 / 33.0), hs * (46732.0 / 5247.0),
            hs * (49.0 / 176.0), hs * (-5103.0 / 18656.0), 5, 0, kk[5]);
    }
    // final y update for step 7
    combine_kernel<<<3600, 256>>>((const float4*)y, (float4*)y,
        (const float4*)kk[0], (const float4*)kk[2], (const float4*)kk[3],
        (const float4*)kk[4], (const float4*)kk[5],
        (float)bf0, (float)bf2, (float)bf3, (float)bf4, (float)bf5);

    // ---- head ----
    gn8_kernel<<<1024, 256>>>(y, t0b, out_gn_g, out_gn_b, 1);
    pool_kernel<<<2048, 256>>>(t0b, pool);
    fc_kernel<<<BATCH, 64>>>(pool, fc_w, fc_b, out);
}

// round 16
// speedup vs baseline: 1.0198x; 1.0198x over previous
#include <cuda_runtime.h>
#include <cuda_fp16.h>
#include <cstdint>

// ---------------- sizes ----------------
#define BATCH 256
#define NY 3686400              // 256*64*15*15
#define H1N (256*64*62*62)
#define H2N (256*64*31*31)

// smem layout for ODE mma conv (R11-proven)
#define MM_HHI 0                // halo A (fp16): 306 rows x 128B
#define MM_BHI 39168            // weights (fp16): 64 rows x 128B
#define MM_STAT 47360           // sums/sumsq/scv/shv: 4 x 64 floats
#define MM_SMEM_BYTES 48384

// smem layout for downsample 4x4/s2 mma conv
#define C4_W 78336              // halo: 612 rows x 128B, then weights 8192B
#define C4_SMEM_BYTES 86528

// ---------------- scratch (device globals, no allocation) ----------------
__device__ float g_h1[H1N];
__device__ float g_h2[H2N];
__device__ float g_y[NY];
__device__ float g_t0[NY];
__device__ float g_t1[NY];
__device__ float g_k[6][NY];
__device__ float g_S1[64 * 225];
__device__ float g_S2[64 * 225];
__device__ float g_pool[256 * 64];
__device__ __half g_w1[9 * 4096];
__device__ __half g_w2[9 * 4096];
__device__ __half g_w4a[16 * 4096];
__device__ __half g_w4b[16 * 4096];

// ---------------- helpers ----------------
__inline__ __device__ float warpSum(float v) {
#pragma unroll
    for (int o = 16; o; o >>= 1) v += __shfl_xor_sync(0xffffffffu, v, o);
    return v;
}
__device__ __forceinline__ uint32_t smem_u32(const void* p) {
    uint32_t a;
    asm("{ .reg .u64 tmp; cvta.to.shared.u64 tmp, %1; cvt.u32.u64 %0, tmp; }"
        : "=r"(a) : "l"(p));
    return a;
}
__device__ __forceinline__ void ldsm4(uint32_t* r, uint32_t addr) {
    asm volatile("ldmatrix.sync.aligned.m8n8.x4.shared.b16 {%0,%1,%2,%3}, [%4];"
        : "=r"(r[0]), "=r"(r[1]), "=r"(r[2]), "=r"(r[3]) : "r"(addr));
}
__device__ __forceinline__ void ldsm2(uint32_t* r, uint32_t addr) {
    asm volatile("ldmatrix.sync.aligned.m8n8.x2.shared.b16 {%0,%1}, [%2];"
        : "=r"(r[0]), "=r"(r[1]) : "r"(addr));
}
__device__ __forceinline__ void mma_fp16(float* c, const uint32_t* a, const uint32_t* b) {
    asm volatile("mma.sync.aligned.m16n8k16.row.col.f32.f16.f16.f32 "
        "{%0,%1,%2,%3}, {%4,%5,%6,%7}, {%8,%9}, {%0,%1,%2,%3};"
        : "+f"(c[0]), "+f"(c[1]), "+f"(c[2]), "+f"(c[3])
        : "r"(a[0]), "r"(a[1]), "r"(a[2]), "r"(a[3]), "r"(b[0]), "r"(b[1]));
}

// shared conv body: tap loop + GN epilogue (input halo already filled & normalized)
__device__ __forceinline__ void conv_body_gn(
    char* smem, uint32_t HHIa, uint32_t BHIa,
    const __half* __restrict__ wq,
    const float* __restrict__ bias, const float* __restrict__ S, float t,
    const float* __restrict__ gamma, const float* __restrict__ beta, int relu,
    float* __restrict__ outp, size_t base, int tid, int wid, int lane)
{
    float* sums  = (float*)(smem + MM_STAT);
    float* sumsq = sums + 64;
    float* scv   = sums + 128;
    float* shv   = sums + 192;

    float acc[2][8][4];
#pragma unroll
    for (int m = 0; m < 2; m++)
#pragma unroll
        for (int n = 0; n < 8; n++)
#pragma unroll
            for (int v = 0; v < 4; v++) acc[m][n][v] = 0.f;

    for (int tap = 0; tap < 9; tap++) {
        __syncthreads();
        {
            const uint4* gh = (const uint4*)(wq + tap * 4096);
            uint4* sh = (uint4*)(smem + MM_BHI);
            for (int i = tid; i < 512; i += 256) sh[i] = gh[i];
        }
        __syncthreads();

        int dd = (tap / 3) * 18 + (tap % 3);
        for (int kt = 0; kt < 4; kt++) {
            uint32_t bh[8][2];
            int nrow = lane & 7;
            int bphys = ((kt * 2 + ((lane >> 3) & 1)) ^ nrow) * 16;
#pragma unroll
            for (int nt = 0; nt < 8; nt++)
                ldsm2(bh[nt], BHIa + (nt * 8 + nrow) * 128 + bphys);
#pragma unroll
            for (int mti = 0; mti < 2; mti++) {
                int mtile = wid + mti * 8;
                if (mtile < 15) {
                    int r = mtile * 18 + (lane & 15) + dd;
                    int aphys = ((kt * 2 + (lane >> 4)) ^ (r & 7)) * 16;
                    uint32_t ah[4];
                    ldsm4(ah, HHIa + r * 128 + aphys);
#pragma unroll
                    for (int nt = 0; nt < 8; nt++)
                        mma_fp16(acc[mti][nt], ah, bh[nt]);
                }
            }
        }
    }

    int row0 = lane >> 2;
    int colb = (lane & 3) * 2;
    bool v1ok = (row0 + 8) < 15;

#pragma unroll
    for (int mti = 0; mti < 2; mti++) {
        int mtile = wid + mti * 8;
        if (mtile >= 15) continue;
        int p0 = mtile * 15 + row0, p1 = p0 + 8;
#pragma unroll
        for (int nt = 0; nt < 8; nt++) {
            int co = nt * 8 + colb;
            float bv0 = __ldg(&bias[co]), bv1 = __ldg(&bias[co + 1]);
            acc[mti][nt][0] += bv0 + t * __ldg(&S[co * 225 + p0]);
            acc[mti][nt][1] += bv1 + t * __ldg(&S[(co + 1) * 225 + p0]);
            if (v1ok) {
                acc[mti][nt][2] += bv0 + t * __ldg(&S[co * 225 + p1]);
                acc[mti][nt][3] += bv1 + t * __ldg(&S[(co + 1) * 225 + p1]);
            }
        }
    }

    if (tid < 64) { sums[tid] = 0.f; sumsq[tid] = 0.f; }
    __syncthreads();
#pragma unroll
    for (int nt = 0; nt < 8; nt++) {
        float sa = 0.f, s2a = 0.f, sb = 0.f, s2b = 0.f;
#pragma unroll
        for (int mti = 0; mti < 2; mti++) {
            int mtile = wid + mti * 8;
            if (mtile >= 15) continue;
            float v0 = acc[mti][nt][0], v1 = acc[mti][nt][1];
            sa += v0; s2a = fmaf(v0, v0, s2a);
            sb += v1; s2b = fmaf(v1, v1, s2b);
            if (v1ok) {
                float v2 = acc[mti][nt][2], v3 = acc[mti][nt][3];
                sa += v2; s2a = fmaf(v2, v2, s2a);
                sb += v3; s2b = fmaf(v3, v3, s2b);
            }
        }
#pragma unroll
        for (int o = 4; o <= 16; o <<= 1) {
            sa  += __shfl_xor_sync(0xffffffffu, sa, o);
            s2a += __shfl_xor_sync(0xffffffffu, s2a, o);
            sb  += __shfl_xor_sync(0xffffffffu, sb, o);
            s2b += __shfl_xor_sync(0xffffffffu, s2b, o);
        }
        if (lane < 4) {
            int co = nt * 8 + lane * 2;
            atomicAdd(&sums[co], sa);  atomicAdd(&sumsq[co], s2a);
            atomicAdd(&sums[co + 1], sb); atomicAdd(&sumsq[co + 1], s2b);
        }
    }
    __syncthreads();
    if (tid < 32) {
        int ca = 2 * tid, cb = ca + 1;
        float mu = (sums[ca] + sums[cb]) * (1.f / 450.f);
        float var = (sumsq[ca] + sumsq[cb]) * (1.f / 450.f) - mu * mu;
        float inv = rsqrtf(var + 1e-5f);
        float sa = inv * gamma[ca], sb2 = inv * gamma[cb];
        scv[ca] = sa; shv[ca] = beta[ca] - mu * sa;
        scv[cb] = sb2; shv[cb] = beta[cb] - mu * sb2;
    }
    __syncthreads();

#pragma unroll
    for (int mti = 0; mti < 2; mti++) {
        int mtile = wid + mti * 8;
        if (mtile >= 15) continue;
        int p0 = mtile * 15 + row0, p1 = p0 + 8;
#pragma unroll
        for (int nt = 0; nt < 8; nt++) {
            int co = nt * 8 + colb;
            float sc0 = scv[co], sh0 = shv[co];
            float sc1 = scv[co + 1], sh1 = shv[co + 1];
            float* oc0 = outp + base + (size_t)co * 225;
            float* oc1 = oc0 + 225;
            float r0 = fmaf(acc[mti][nt][0], sc0, sh0);
            float r1 = fmaf(acc[mti][nt][1], sc1, sh1);
            if (relu) { r0 = fmaxf(r0, 0.f); r1 = fmaxf(r1, 0.f); }
            oc0[p0] = r0; oc1[p0] = r1;
            if (v1ok) {
                float r2 = fmaf(acc[mti][nt][2], sc0, sh0);
                float r3 = fmaf(acc[mti][nt][3], sc1, sh1);
                if (relu) { r2 = fmaxf(r2, 0.f); r3 = fmaxf(r3, 0.f); }
                oc0[p1] = r2; oc1[p1] = r3;
            }
        }
    }
}

// ---------------- conv1: 1->64, 3x3, valid ----------------
__global__ void conv1_kernel(const float* __restrict__ x, float* __restrict__ out,
                             const float* __restrict__ w, const float* __restrict__ bias)
{
    __shared__ float sx[18][18];
    __shared__ float swt[64 * 9];
    __shared__ float sb[64];
    int b = blockIdx.y;
    int tileX = blockIdx.x & 3, tileY = blockIdx.x >> 2;
    int tx = threadIdx.x, ty = threadIdx.y;
    int tid = ty * 16 + tx;

    for (int s = tid; s < 576; s += 256) swt[s] = w[s];
    if (tid < 64) sb[tid] = bias[tid];

    const float* xb = x + (size_t)b * 64 * 64;
    int ox0 = tileX * 16, oy0 = tileY * 16;
    for (int s = tid; s < 18 * 18; s += 256) {
        int r = s / 18, c = s % 18;
        int iy = oy0 + r, ix = ox0 + c;
        sx[r][c] = (iy < 64 && ix < 64) ? xb[iy * 64 + ix] : 0.f;
    }
    __syncthreads();

    int ox = ox0 + tx, oy = oy0 + ty;
    if (ox >= 62 || oy >= 62) return;

    float v[9];
#pragma unroll
    for (int ky = 0; ky < 3; ky++)
#pragma unroll
        for (int kx = 0; kx < 3; kx++)
            v[ky * 3 + kx] = sx[ty + ky][tx + kx];

    float* ob = out + (size_t)b * 64 * 3844 + oy * 62 + ox;
#pragma unroll 4
    for (int co = 0; co < 64; co++) {
        float a = sb[co];
#pragma unroll
        for (int k = 0; k < 9; k++) a = fmaf(swt[co * 9 + k], v[k], a);
        ob[(size_t)co * 3844] = a;
    }
}

// ---------------- generic GroupNorm (big HW) ----------------
__global__ void gn_big_kernel(const float* __restrict__ in, float* __restrict__ out,
                              const float* __restrict__ gamma, const float* __restrict__ beta,
                              int HW, int relu)
{
    __shared__ float rs[8], rs2[8], stats[2];
    int bg = blockIdx.x;
    int c0 = (bg & 31) * 2;
    size_t base = (size_t)bg * 2 * HW;
    int n = 2 * HW;
    float s = 0.f, s2 = 0.f;
    for (int i = threadIdx.x; i < n; i += 256) {
        float v = in[base + i];
        s += v; s2 = fmaf(v, v, s2);
    }
    s = warpSum(s); s2 = warpSum(s2);
    int wi = threadIdx.x >> 5, lane = threadIdx.x & 31;
    if (lane == 0) { rs[wi] = s; rs2[wi] = s2; }
    __syncthreads();
    if (threadIdx.x == 0) {
        float a = 0.f, bb = 0.f;
#pragma unroll
        for (int i = 0; i < 8; i++) { a += rs[i]; bb += rs2[i]; }
        float mu = a / (float)n;
        stats[0] = mu;
        stats[1] = rsqrtf(bb / (float)n - mu * mu + 1e-5f);
    }
    __syncthreads();
    float mu = stats[0], inv = stats[1];
    float sc0 = inv * gamma[c0],     sh0 = beta[c0]     - mu * sc0;
    float sc1 = inv * gamma[c0 + 1], sh1 = beta[c0 + 1] - mu * sc1;
    for (int i = threadIdx.x; i < n; i += 256) {
        float v = in[base + i];
        float r = (i < HW) ? fmaf(v, sc0, sh0) : fmaf(v, sc1, sh1);
        if (relu) r = fmaxf(r, 0.f);
        out[base + i] = r;
    }
}

// ---------------- GroupNorm 15x15: 8 groups per 256-thr block (head only) ----------------
__global__ void gn8_kernel(const float* __restrict__ in, float* __restrict__ out,
                           const float* __restrict__ gamma, const float* __restrict__ beta,
                           int relu)
{
    int wid = threadIdx.x >> 5, lane = threadIdx.x & 31;
    int bg = blockIdx.x * 8 + wid;
    size_t base = (size_t)bg * 450;
    int c0 = (bg & 31) * 2;
    float v[15];
    float s = 0.f, s2 = 0.f;
#pragma unroll
    for (int k = 0; k < 15; k++) {
        int i = k * 32 + lane;
        float xv = (i < 450) ? in[base + i] : 0.f;
        v[k] = xv;
        s += xv; s2 = fmaf(xv, xv, s2);
    }
    s = warpSum(s); s2 = warpSum(s2);
    float mu = s * (1.f / 450.f);
    float inv = rsqrtf(s2 * (1.f / 450.f) - mu * mu + 1e-5f);
    float sc0 = inv * gamma[c0],     sh0 = beta[c0]     - mu * sc0;
    float sc1 = inv * gamma[c0 + 1], sh1 = beta[c0 + 1] - mu * sc1;
#pragma unroll
    for (int k = 0; k < 15; k++) {
        int i = k * 32 + lane;
        if (i < 450) {
            float r = (i < 225) ? fmaf(v[k], sc0, sh0) : fmaf(v[k], sc1, sh1);
            if (relu) r = fmaxf(r, 0.f);
            out[base + i] = r;
        }
    }
}

// ---------------- precompute S[co][p] ----------------
__global__ void precomp_s_kernel(const float* __restrict__ w, float* __restrict__ S)
{
    int co = blockIdx.x;
    int p = threadIdx.x;
    int y = p / 15, x = p % 15;
    float a = 0.f;
#pragma unroll
    for (int ky = 0; ky < 3; ky++) {
        int iy = y - 1 + ky;
        if ((unsigned)iy < 15u) {
#pragma unroll
            for (int kx = 0; kx < 3; kx++) {
                int ix = x - 1 + kx;
                if ((unsigned)ix < 15u) a += w[(size_t)co * 65 * 9 + ky * 3 + kx];
            }
        }
    }
    S[co * 225 + p] = a;
}

// ---------------- precompute swizzled fp16 weights per tap (3x3 ODE convs) ----------------
__global__ void precomp_w_kernel(const float* __restrict__ w, __half* __restrict__ hi)
{
    int tap = blockIdx.x;
    for (int s = threadIdx.x; s < 4096; s += 256) {
        int co = s >> 6, ci = s & 63;
        float v = w[((size_t)co * 65 + ci + 1) * 9 + tap];
        int pos = tap * 4096 + co * 64 + ((((ci >> 3) ^ (co & 7)) << 3) + (ci & 7));
        hi[pos] = __float2half(v);
    }
}

// ---------------- precompute swizzled fp16 weights per tap (4x4 downsample convs) ----------------
__global__ void precomp_w4_kernel(const float* __restrict__ w, __half* __restrict__ hi)
{
    int tap = blockIdx.x;
    for (int s = threadIdx.x; s < 4096; s += 256) {
        int co = s >> 6, ci = s & 63;
        float v = w[(((size_t)co * 64) + ci) * 16 + tap];
        int pos = tap * 4096 + co * 64 + ((((ci >> 3) ^ (co & 7)) << 3) + (ci & 7));
        hi[pos] = __float2half(v);
    }
}

// ---------------- downsample conv 4x4 stride2 pad1 via fp16 mma ----------------
__global__ void __launch_bounds__(256, 2)
conv4_mma(const float* __restrict__ in, float* __restrict__ out,
          const __half* __restrict__ wq, const float* __restrict__ bias,
          int Hin, int Hout)
{
    extern __shared__ __align__(128) char smem[];
    uint32_t smBase = smem_u32(smem);
    const uint32_t HA = smBase;
    const uint32_t BA = smBase + C4_W;

    int tid = threadIdx.x;
    int wid = tid >> 5, lane = tid & 31;
    int b = blockIdx.z;
    int ox0 = blockIdx.x * 16, oy0 = blockIdx.y * 8;
    int iy0 = 2 * oy0 - 1, ix0 = 2 * ox0 - 1;

    {
        uint4 z = make_uint4(0u, 0u, 0u, 0u);
        uint4* h4 = (uint4*)smem;
        for (int i = tid; i < 4896; i += 256) h4[i] = z;
    }
    __syncthreads();
    {
        __half* hh = (__half*)smem;
        const float* inb = in + ((size_t)b * 64) * Hin * Hin;
        for (int s = tid; s < 64 * 612; s += 256) {
            int ci = s / 612, rr = s % 612;
            int ly = rr / 34, lx = rr % 34;
            int iy = iy0 + ly, ix = ix0 + lx;
            if ((unsigned)iy < (unsigned)Hin && (unsigned)ix < (unsigned)Hin) {
                float v = inb[(size_t)ci * Hin * Hin + iy * Hin + ix];
                int off = rr * 64 + ((((ci >> 3) ^ (rr & 7)) << 3) + (ci & 7));
                hh[off] = __float2half(v);
            }
        }
    }

    float acc[8][4];
#pragma unroll
    for (int n = 0; n < 8; n++)
#pragma unroll
        for (int v = 0; v < 4; v++) acc[n][v] = 0.f;

    for (int tap = 0; tap < 16; tap++) {
        __syncthreads();
        {
            const uint4* gh = (const uint4*)(wq + tap * 4096);
            uint4* sh = (uint4*)(smem + C4_W);
            for (int i = tid; i < 512; i += 256) sh[i] = gh[i];
        }
        __syncthreads();

        int ky = tap >> 2, kx = tap & 3;
        for (int kt = 0; kt < 4; kt++) {
            uint32_t bh[8][2];
            int nrow = lane & 7;
            int bphys = ((kt * 2 + ((lane >> 3) & 1)) ^ nrow) * 16;
#pragma unroll
            for (int nt = 0; nt < 8; nt++)
                ldsm2(bh[nt], BA + (nt * 8 + nrow) * 128 + bphys);

            int r = (2 * wid + ky) * 34 + 2 * (lane & 15) + kx;
            int aphys = ((kt * 2 + (lane >> 4)) ^ (r & 7)) * 16;
            uint32_t ah[4];
            ldsm4(ah, HA + r * 128 + aphys);
#pragma unroll
            for (int nt = 0; nt < 8; nt++)
                mma_fp16(acc[nt], ah, bh[nt]);
        }
    }

    int oy = oy0 + wid;
    if (oy < Hout) {
        int row0 = lane >> 2;
        int colb = (lane & 3) * 2;
        int oxa = ox0 + row0, oxb = ox0 + row0 + 8;
        int HW = Hout * Hout;
        float* ob = out + ((size_t)b * 64) * HW + oy * Hout;
#pragma unroll
        for (int nt = 0; nt < 8; nt++) {
            int co = nt * 8 + colb;
            float bv0 = __ldg(&bias[co]), bv1 = __ldg(&bias[co + 1]);
            if (oxa < Hout) {
                ob[(size_t)co * HW + oxa] = acc[nt][0] + bv0;
                ob[(size_t)(co + 1) * HW + oxa] = acc[nt][1] + bv1;
            }
            if (oxb < Hout) {
                ob[(size_t)co * HW + oxb] = acc[nt][2] + bv0;
                ob[(size_t)(co + 1) * HW + oxb] = acc[nt][3] + bv1;
            }
        }
    }
}

// ---------------- feval conv1: fused combine + GN1 + relu prologue, conv, GN2 epilogue ----------------
__global__ void __launch_bounds__(256, 2)
ode_conv1_gn(float* __restrict__ y,
             const float* __restrict__ k0, const float* __restrict__ k1,
             const float* __restrict__ k2, const float* __restrict__ k3,
             const float* __restrict__ k4,
             float c0, float c1, float c2, float c3, float c4, int nk, int writeY,
             const float* __restrict__ g1, const float* __restrict__ bb1,
             const __half* __restrict__ wq,
             const float* __restrict__ bias, const float* __restrict__ S, float t,
             const float* __restrict__ gamma, const float* __restrict__ beta,
             float* __restrict__ outp)
{
    extern __shared__ __align__(128) char smem[];
    uint32_t smBase = smem_u32(smem);
    float* sums  = (float*)(smem + MM_STAT);
    float* sumsq = sums + 64;
    float* scv   = sums + 128;
    float* shv   = sums + 192;

    int tid = threadIdx.x;
    int wid = tid >> 5, lane = tid & 31;
    int b = blockIdx.x;
    size_t base = (size_t)b * 14400;
    __half* hh = (__half*)smem;

    // zero halo
    {
        uint4 z = make_uint4(0u, 0u, 0u, 0u);
        uint4* h4 = (uint4*)smem;
        for (int i = tid; i < 2448; i += 256) h4[i] = z;
    }
    __syncthreads();

    // combine + GN1 stats; write raw fp16 halo. ch = tid>>2, q = tid&3
    int ch = tid >> 2, q = tid & 3;
    {
        float s = 0.f, s2 = 0.f;
        for (int j = q; j < 225; j += 4) {
            size_t idx = base + ch * 225 + j;
            float v = y[idx];
            if (nk > 0) v = fmaf(c0, k0[idx], v);
            if (nk > 1) v = fmaf(c1, k1[idx], v);
            if (nk > 2) v = fmaf(c2, k2[idx], v);
            if (nk > 3) v = fmaf(c3, k3[idx], v);
            if (nk > 4) v = fmaf(c4, k4[idx], v);
            if (writeY) y[idx] = v;
            s += v; s2 = fmaf(v, v, s2);
            int r = (j / 15 + 1) * 18 + (j % 15) + 1;
            hh[r * 64 + ((((ch >> 3) ^ (r & 7)) << 3) + (ch & 7))] = __float2half(v);
        }
        s  += __shfl_xor_sync(0xffffffffu, s, 1);
        s  += __shfl_xor_sync(0xffffffffu, s, 2);
        s2 += __shfl_xor_sync(0xffffffffu, s2, 1);
        s2 += __shfl_xor_sync(0xffffffffu, s2, 2);
        if (q == 0) { sums[ch] = s; sumsq[ch] = s2; }
    }
    __syncthreads();
    if (tid < 32) {
        int ca = 2 * tid, cb = ca + 1;
        float mu = (sums[ca] + sums[cb]) * (1.f / 450.f);
        float var = (sumsq[ca] + sumsq[cb]) * (1.f / 450.f) - mu * mu;
        float inv = rsqrtf(var + 1e-5f);
        float sa = inv * g1[ca], sb2 = inv * g1[cb];
        scv[ca] = sa; shv[ca] = bb1[ca] - mu * sa;
        scv[cb] = sb2; shv[cb] = bb1[cb] - mu * sb2;
    }
    __syncthreads();
    // normalize + relu halo in place
    {
        float sc = scv[ch], sh = shv[ch];
        for (int j = q; j < 225; j += 4) {
            int r = (j / 15 + 1) * 18 + (j % 15) + 1;
            int off = r * 64 + ((((ch >> 3) ^ (r & 7)) << 3) + (ch & 7));
            float v = __half2float(hh[off]);
            hh[off] = __float2half(fmaxf(fmaf(v, sc, sh), 0.f));
        }
    }
    // conv body's leading sync orders the normalize writes

    conv_body_gn(smem, smBase + MM_HHI, smBase + MM_BHI, wq, bias, S, t,
                 gamma, beta, 1, outp, base, tid, wid, lane);
}

// ---------------- feval conv2: plain fill prologue, conv, GN3 epilogue ----------------
__global__ void __launch_bounds__(256, 2)
ode_conv_gn(const float* __restrict__ in, float* __restrict__ out,
            const __half* __restrict__ wq,
            const float* __restrict__ bias, const float* __restrict__ S, float t,
            const float* __restrict__ gamma, const float* __restrict__ beta, int relu)
{
    extern __shared__ __align__(128) char smem[];
    uint32_t smBase = smem_u32(smem);

    int tid = threadIdx.x;
    int wid = tid >> 5, lane = tid & 31;
    int b = blockIdx.x;
    size_t base = (size_t)b * 14400;

    {
        uint4 z = make_uint4(0u, 0u, 0u, 0u);
        uint4* h4 = (uint4*)smem;
        for (int i = tid; i < 2448; i += 256) h4[i] = z;
    }
    __syncthreads();
    {
        __half* hh = (__half*)smem;
        for (int s = tid; s < 14400; s += 256) {
            int ci = s / 225, p = s % 225;
            float v = in[base + s];
            int r = (p / 15 + 1) * 18 + (p % 15) + 1;
            hh[r * 64 + ((((ci >> 3) ^ (r & 7)) << 3) + (ci & 7))] = __float2half(v);
        }
    }

    conv_body_gn(smem, smBase + MM_HHI, smBase + MM_BHI, wq, bias, S, t,
                 gamma, beta, relu, out, base, tid, wid, lane);
}

// ---------------- final combine ----------------
__global__ void combine_kernel(const float4* __restrict__ y, float4* __restrict__ dst,
                               const float4* __restrict__ p0, const float4* __restrict__ p1,
                               const float4* __restrict__ p2, const float4* __restrict__ p3,
                               const float4* __restrict__ p4,
                               float c0, float c1, float c2, float c3, float c4)
{
    int i = blockIdx.x * 256 + threadIdx.x;
    float4 a = y[i];
    float4 t;
    t = p0[i]; a.x = fmaf(c0, t.x, a.x); a.y = fmaf(c0, t.y, a.y); a.z = fmaf(c0, t.z, a.z); a.w = fmaf(c0, t.w, a.w);
    t = p1[i]; a.x = fmaf(c1, t.x, a.x); a.y = fmaf(c1, t.y, a.y); a.z = fmaf(c1, t.z, a.z); a.w = fmaf(c1, t.w, a.w);
    t = p2[i]; a.x = fmaf(c2, t.x, a.x); a.y = fmaf(c2, t.y, a.y); a.z = fmaf(c2, t.z, a.z); a.w = fmaf(c2, t.w, a.w);
    t = p3[i]; a.x = fmaf(c3, t.x, a.x); a.y = fmaf(c3, t.y, a.y); a.z = fmaf(c3, t.z, a.z); a.w = fmaf(c3, t.w, a.w);
    t = p4[i]; a.x = fmaf(c4, t.x, a.x); a.y = fmaf(c4, t.y, a.y); a.z = fmaf(c4, t.z, a.z); a.w = fmaf(c4, t.w, a.w);
    dst[i] = a;
}

// ---------------- global mean pool ----------------
__global__ void pool_kernel(const float* __restrict__ in, float* __restrict__ out)
{
    int gw = (blockIdx.x * 256 + threadIdx.x) >> 5;
    int lane = threadIdx.x & 31;
    const float* p = in + (size_t)gw * 225;
    float s = 0.f;
    for (int i = lane; i < 225; i += 32) s += p[i];
    s = warpSum(s);
    if (lane == 0) out[gw] = s * (1.f / 225.f);
}

// ---------------- FC 64->10 ----------------
__global__ void fc_kernel(const float* __restrict__ pool, const float* __restrict__ w,
                          const float* __restrict__ bias, float* __restrict__ out)
{
    __shared__ float sp[64];
    int b = blockIdx.x;
    sp[threadIdx.x] = pool[b * 64 + threadIdx.x];
    __syncthreads();
    if (threadIdx.x < 10) {
        float a = bias[threadIdx.x];
#pragma unroll
        for (int c = 0; c < 64; c++) a = fmaf(sp[c], __ldg(&w[threadIdx.x * 64 + c]), a);
        out[b * 10 + threadIdx.x] = a;
    }
}

// ---------------- launch ----------------
extern "C" void kernel_launch(void* const* d_in, const int* in_sizes, int n_in,
                              void* d_out, int out_size)
{
    const float* x        = (const float*)d_in[0];
    const float* conv1_w  = (const float*)d_in[1];
    const float* conv1_b  = (const float*)d_in[2];
    const float* gn1_g    = (const float*)d_in[3];
    const float* gn1_b    = (const float*)d_in[4];
    const float* conv2_w  = (const float*)d_in[5];
    const float* conv2_b  = (const float*)d_in[6];
    const float* gn2_g    = (const float*)d_in[7];
    const float* gn2_b    = (const float*)d_in[8];
    const float* conv3_w  = (const float*)d_in[9];
    const float* conv3_b  = (const float*)d_in[10];
    const float* f_gn1_g  = (const float*)d_in[11];
    const float* f_gn1_b  = (const float*)d_in[12];
    const float* f_conv1_w= (const float*)d_in[13];
    const float* f_conv1_b= (const float*)d_in[14];
    const float* f_gn2_g  = (const float*)d_in[15];
    const float* f_gn2_b  = (const float*)d_in[16];
    const float* f_conv2_w= (const float*)d_in[17];
    const float* f_conv2_b= (const float*)d_in[18];
    const float* f_gn3_g  = (const float*)d_in[19];
    const float* f_gn3_b  = (const float*)d_in[20];
    const float* out_gn_g = (const float*)d_in[21];
    const float* out_gn_b = (const float*)d_in[22];
    const float* fc_w     = (const float*)d_in[23];
    const float* fc_b     = (const float*)d_in[24];
    float* out = (float*)d_out;

    float *h1, *h2, *y, *t0b, *t1b, *kbase, *S1, *S2, *pool;
    __half *w1q, *w2q, *w4a, *w4b;
    cudaGetSymbolAddress((void**)&h1, g_h1);
    cudaGetSymbolAddress((void**)&h2, g_h2);
    cudaGetSymbolAddress((void**)&y, g_y);
    cudaGetSymbolAddress((void**)&t0b, g_t0);
    cudaGetSymbolAddress((void**)&t1b, g_t1);
    cudaGetSymbolAddress((void**)&kbase, g_k);
    cudaGetSymbolAddress((void**)&S1, g_S1);
    cudaGetSymbolAddress((void**)&S2, g_S2);
    cudaGetSymbolAddress((void**)&pool, g_pool);
    cudaGetSymbolAddress((void**)&w1q, g_w1);
    cudaGetSymbolAddress((void**)&w2q, g_w2);
    cudaGetSymbolAddress((void**)&w4a, g_w4a);
    cudaGetSymbolAddress((void**)&w4b, g_w4b);
    float* kk[6];
    for (int i = 0; i < 6; i++) kk[i] = kbase + (size_t)i * NY;

    cudaFuncSetAttribute(ode_conv_gn, cudaFuncAttributeMaxDynamicSharedMemorySize, MM_SMEM_BYTES);
    cudaFuncSetAttribute(ode_conv1_gn, cudaFuncAttributeMaxDynamicSharedMemorySize, MM_SMEM_BYTES);
    cudaFuncSetAttribute(conv4_mma, cudaFuncAttributeMaxDynamicSharedMemorySize, C4_SMEM_BYTES);

    // ---- downsampling ----
    conv1_kernel<<<dim3(16, BATCH), dim3(16, 16)>>>(x, h1, conv1_w, conv1_b);
    gn_big_kernel<<<BATCH * 32, 256>>>(h1, h1, gn1_g, gn1_b, 62 * 62, 1);
    precomp_w4_kernel<<<16, 256>>>(conv2_w, w4a);
    precomp_w4_kernel<<<16, 256>>>(conv3_w, w4b);
    conv4_mma<<<dim3(2, 4, BATCH), 256, C4_SMEM_BYTES>>>(h1, h2, w4a, conv2_b, 62, 31);
    gn_big_kernel<<<BATCH * 32, 256>>>(h2, h2, gn2_g, gn2_b, 31 * 31, 1);
    conv4_mma<<<dim3(1, 2, BATCH), 256, C4_SMEM_BYTES>>>(h2, y, w4b, conv3_b, 31, 15);

    precomp_s_kernel<<<64, 225>>>(f_conv1_w, S1);
    precomp_s_kernel<<<64, 225>>>(f_conv2_w, S2);
    precomp_w_kernel<<<9, 256>>>(f_conv1_w, w1q);
    precomp_w_kernel<<<9, 256>>>(f_conv2_w, w2q);

    // feval: [combine+GN1+conv1+GN2] -> [conv2+GN3] -> k
    auto fev = [&](float t, const float* p0, const float* p1, const float* p2,
                   const float* p3, const float* p4,
                   double c0, double c1, double c2, double c3, double c4,
                   int nk, int writeY, float* kout) {
        ode_conv1_gn<<<BATCH, 256, MM_SMEM_BYTES>>>(
            y, p0 ? p0 : y, p1 ? p1 : y, p2 ? p2 : y, p3 ? p3 : y, p4 ? p4 : y,
            (float)c0, (float)c1, (float)c2, (float)c3, (float)c4, nk, writeY,
            f_gn1_g, f_gn1_b, w1q, f_conv1_b, S1, t, f_gn2_g, f_gn2_b, t1b);
        ode_conv_gn<<<BATCH, 256, MM_SMEM_BYTES>>>(t1b, kout, w2q, f_conv2_b, S2, t,
                                                   f_gn3_g, f_gn3_b, 0);
    };

    const double hs = 1.0 / 8.0;
    const double bf0 = hs * (35.0 / 384.0),  bf2 = hs * (500.0 / 1113.0);
    const double bf3 = hs * (125.0 / 192.0), bf4 = hs * (-2187.0 / 6784.0);
    const double bf5 = hs * (11.0 / 84.0);

    for (int st = 0; st < 8; st++) {
        double T0 = st * hs;
        if (st == 0)
            fev((float)T0, 0, 0, 0, 0, 0, 0, 0, 0, 0, 0, 0, 0, kk[0]);
        else
            fev((float)T0, kk[0], kk[2], kk[3], kk[4], kk[5],
                bf0, bf2, bf3, bf4, bf5, 5, 1, kk[0]);
        fev((float)(T0 + hs / 5.0), kk[0], 0, 0, 0, 0,
            hs * (1.0 / 5.0), 0, 0, 0, 0, 1, 0, kk[1]);
        fev((float)(T0 + 0.3 * hs), kk[0], kk[1], 0, 0, 0,
            hs * (3.0 / 40.0), hs * (9.0 / 40.0), 0, 0, 0, 2, 0, kk[2]);
        fev((float)(T0 + 0.8 * hs), kk[0], kk[1], kk[2], 0, 0,
            hs * (44.0 / 45.0), hs * (-56.0 / 15.0), hs * (32.0 / 9.0), 0, 0, 3, 0, kk[3]);
        fev((float)(T0 + (8.0 / 9.0) * hs), kk[0], kk[1], kk[2], kk[3], 0,
            hs * (19372.0 / 6561.0), hs * (-25360.0 / 2187.0),
            hs * (64448.0 / 6561.0), hs * (-212.0 / 729.0), 0, 4, 0, kk[4]);
        fev((float)(T0 + hs), kk[0], kk[1], kk[2], kk[3], kk[4],
            hs * (9017.0 / 3168.0), hs * (-355.0 / 33.0), hs * (46732.0 / 5247.0),
            hs * (49.0 / 176.0), hs * (-5103.0 / 18656.0), 5, 0, kk[5]);
    }
    // final y update for step 7
    combine_kernel<<<3600, 256>>>((const float4*)y, (float4*)y,
        (const float4*)kk[0], (const float4*)kk[2], (const float4*)kk[3],
        (const float4*)kk[4], (const float4*)kk[5],
        (float)bf0, (float)bf2, (float)bf3, (float)bf4, (float)bf5);

    // ---- head ----
    gn8_kernel<<<1024, 256>>>(y, t0b, out_gn_g, out_gn_b, 1);
    pool_kernel<<<2048, 256>>>(t0b, pool);
    fc_kernel<<<BATCH, 64>>>(pool, fc_w, fc_b, out);
}

// round 17
// speedup vs baseline: 1.5451x; 1.5152x over previous
#include <cuda_runtime.h>
#include <cuda_fp16.h>
#include <cstdint>

// ---------------- sizes ----------------
#define BATCH 256
#define NY 3686400              // 256*64*15*15
#define H1N (256*64*62*62)
#define H2N (256*64*31*31)

// smem layout for ODE mma conv
#define MM_HHI 0                // halo A (fp16): 306 rows x 128B
#define MM_BHI 39168            // weights (fp16): 64 rows x 128B
#define MM_STAT 47360           // sums/sumsq/scv/shv: 4 x 64 floats
#define MM_SMEM_BYTES 48384

// smem layout for downsample 4x4/s2 mma conv
#define C4_W 78336              // halo: 612 rows x 128B, then weights 8192B
#define C4_SMEM_BYTES 86528

// ---------------- scratch (device globals, no allocation) ----------------
__device__ float g_h1[H1N];
__device__ float g_h2[H2N];
__device__ float g_y[NY];
__device__ float g_t0[NY];
__device__ float g_k[6][NY];
__device__ float g_S1[64 * 225];
__device__ float g_S2[64 * 225];
__device__ float g_pool[256 * 64];
__device__ __half g_w1[9 * 4096];
__device__ __half g_w2[9 * 4096];
__device__ __half g_w4a[16 * 4096];
__device__ __half g_w4b[16 * 4096];

// ---------------- helpers ----------------
__inline__ __device__ float warpSum(float v) {
#pragma unroll
    for (int o = 16; o; o >>= 1) v += __shfl_xor_sync(0xffffffffu, v, o);
    return v;
}
__device__ __forceinline__ uint32_t smem_u32(const void* p) {
    uint32_t a;
    asm("{ .reg .u64 tmp; cvta.to.shared.u64 tmp, %1; cvt.u32.u64 %0, tmp; }"
        : "=r"(a) : "l"(p));
    return a;
}
__device__ __forceinline__ void ldsm4(uint32_t* r, uint32_t addr) {
    asm volatile("ldmatrix.sync.aligned.m8n8.x4.shared.b16 {%0,%1,%2,%3}, [%4];"
        : "=r"(r[0]), "=r"(r[1]), "=r"(r[2]), "=r"(r[3]) : "r"(addr));
}
__device__ __forceinline__ void ldsm2(uint32_t* r, uint32_t addr) {
    asm volatile("ldmatrix.sync.aligned.m8n8.x2.shared.b16 {%0,%1}, [%2];"
        : "=r"(r[0]), "=r"(r[1]) : "r"(addr));
}
__device__ __forceinline__ void mma_fp16(float* c, const uint32_t* a, const uint32_t* b) {
    asm volatile("mma.sync.aligned.m16n8k16.row.col.f32.f16.f16.f32 "
        "{%0,%1,%2,%3}, {%4,%5,%6,%7}, {%8,%9}, {%0,%1,%2,%3};"
        : "+f"(c[0]), "+f"(c[1]), "+f"(c[2]), "+f"(c[3])
        : "r"(a[0]), "r"(a[1]), "r"(a[2]), "r"(a[3]), "r"(b[0]), "r"(b[1]));
}

// ---------------- conv tap loop (R11/R13-proven) ----------------
__device__ __forceinline__ void conv_taps(
    char* smem, uint32_t HHIa, uint32_t BHIa, const __half* __restrict__ wq,
    int tid, int wid, int lane, float acc[2][8][4])
{
#pragma unroll
    for (int m = 0; m < 2; m++)
#pragma unroll
        for (int n = 0; n < 8; n++)
#pragma unroll
            for (int v = 0; v < 4; v++) acc[m][n][v] = 0.f;

    for (int tap = 0; tap < 9; tap++) {
        __syncthreads();
        {
            const uint4* gh = (const uint4*)(wq + tap * 4096);
            uint4* sh = (uint4*)(smem + MM_BHI);
            for (int i = tid; i < 512; i += 256) sh[i] = gh[i];
        }
        __syncthreads();

        int dd = (tap / 3) * 18 + (tap % 3);
        for (int kt = 0; kt < 4; kt++) {
            uint32_t bh[8][2];
            int nrow = lane & 7;
            int bphys = ((kt * 2 + ((lane >> 3) & 1)) ^ nrow) * 16;
#pragma unroll
            for (int nt = 0; nt < 8; nt++)
                ldsm2(bh[nt], BHIa + (nt * 8 + nrow) * 128 + bphys);
#pragma unroll
            for (int mti = 0; mti < 2; mti++) {
                int mtile = wid + mti * 8;
                if (mtile < 15) {
                    int r = mtile * 18 + (lane & 15) + dd;
                    int aphys = ((kt * 2 + (lane >> 4)) ^ (r & 7)) * 16;
                    uint32_t ah[4];
                    ldsm4(ah, HHIa + r * 128 + aphys);
#pragma unroll
                    for (int nt = 0; nt < 8; nt++)
                        mma_fp16(acc[mti][nt], ah, bh[nt]);
                }
            }
        }
    }
}

// bias + t*S into acc, then GN stats -> scv/shv  (smem stat arrays)
__device__ __forceinline__ void gn_stats_from_acc(
    char* smem, float acc[2][8][4],
    const float* __restrict__ bias, const float* __restrict__ S, float t,
    const float* __restrict__ gamma, const float* __restrict__ beta,
    int tid, int wid, int lane, int row0, int colb, bool v1ok)
{
    float* sums  = (float*)(smem + MM_STAT);
    float* sumsq = sums + 64;
    float* scv   = sums + 128;
    float* shv   = sums + 192;

#pragma unroll
    for (int mti = 0; mti < 2; mti++) {
        int mtile = wid + mti * 8;
        if (mtile >= 15) continue;
        int p0 = mtile * 15 + row0, p1 = p0 + 8;
#pragma unroll
        for (int nt = 0; nt < 8; nt++) {
            int co = nt * 8 + colb;
            float bv0 = __ldg(&bias[co]), bv1 = __ldg(&bias[co + 1]);
            acc[mti][nt][0] += bv0 + t * __ldg(&S[co * 225 + p0]);
            acc[mti][nt][1] += bv1 + t * __ldg(&S[(co + 1) * 225 + p0]);
            if (v1ok) {
                acc[mti][nt][2] += bv0 + t * __ldg(&S[co * 225 + p1]);
                acc[mti][nt][3] += bv1 + t * __ldg(&S[(co + 1) * 225 + p1]);
            }
        }
    }

    if (tid < 64) { sums[tid] = 0.f; sumsq[tid] = 0.f; }
    __syncthreads();   // also orders prior halo reads before any halo rewrite
#pragma unroll
    for (int nt = 0; nt < 8; nt++) {
        float sa = 0.f, s2a = 0.f, sb = 0.f, s2b = 0.f;
#pragma unroll
        for (int mti = 0; mti < 2; mti++) {
            int mtile = wid + mti * 8;
            if (mtile >= 15) continue;
            float v0 = acc[mti][nt][0], v1 = acc[mti][nt][1];
            sa += v0; s2a = fmaf(v0, v0, s2a);
            sb += v1; s2b = fmaf(v1, v1, s2b);
            if (v1ok) {
                float v2 = acc[mti][nt][2], v3 = acc[mti][nt][3];
                sa += v2; s2a = fmaf(v2, v2, s2a);
                sb += v3; s2b = fmaf(v3, v3, s2b);
            }
        }
#pragma unroll
        for (int o = 4; o <= 16; o <<= 1) {
            sa  += __shfl_xor_sync(0xffffffffu, sa, o);
            s2a += __shfl_xor_sync(0xffffffffu, s2a, o);
            sb  += __shfl_xor_sync(0xffffffffu, sb, o);
            s2b += __shfl_xor_sync(0xffffffffu, s2b, o);
        }
        if (lane < 4) {
            int co = nt * 8 + lane * 2;
            atomicAdd(&sums[co], sa);  atomicAdd(&sumsq[co], s2a);
            atomicAdd(&sums[co + 1], sb); atomicAdd(&sumsq[co + 1], s2b);
        }
    }
    __syncthreads();
    if (tid < 32) {
        int ca = 2 * tid, cb = ca + 1;
        float mu = (sums[ca] + sums[cb]) * (1.f / 450.f);
        float var = (sumsq[ca] + sumsq[cb]) * (1.f / 450.f) - mu * mu;
        float inv = rsqrtf(var + 1e-5f);
        float sa = inv * gamma[ca], sb2 = inv * gamma[cb];
        scv[ca] = sa; shv[ca] = beta[ca] - mu * sa;
        scv[cb] = sb2; shv[cb] = beta[cb] - mu * sb2;
    }
    __syncthreads();
}

// ---------------- fully fused ODE feval ----------------
// [combine + GN1 + relu] -> conv1 -> [GN2 + relu -> halo] -> conv2 -> [GN3 -> kout]
// grid BATCH, block 256, dyn smem MM_SMEM_BYTES
__global__ void __launch_bounds__(256, 2)
feval_fused(float* __restrict__ y,
            const float* __restrict__ k0, const float* __restrict__ k1,
            const float* __restrict__ k2, const float* __restrict__ k3,
            const float* __restrict__ k4,
            float c0, float c1, float c2, float c3, float c4, int nk, int writeY,
            const float* __restrict__ g1, const float* __restrict__ bb1,
            const __half* __restrict__ w1q, const float* __restrict__ b1,
            const float* __restrict__ S1,
            const float* __restrict__ g2, const float* __restrict__ bb2,
            const __half* __restrict__ w2q, const float* __restrict__ b2,
            const float* __restrict__ S2,
            const float* __restrict__ g3, const float* __restrict__ bb3,
            float t, float* __restrict__ kout)
{
    extern __shared__ __align__(128) char smem[];
    uint32_t smBase = smem_u32(smem);
    __half* hh = (__half*)smem;

    int tid = threadIdx.x;
    int wid = tid >> 5, lane = tid & 31;
    int b = blockIdx.x;
    size_t base = (size_t)b * 14400;

    // zero halo
    {
        uint4 z = make_uint4(0u, 0u, 0u, 0u);
        uint4* h4 = (uint4*)smem;
        for (int i = tid; i < 2448; i += 256) h4[i] = z;
    }
    __syncthreads();

    // P1: combine + GN1 + relu (coalesced, per-warp groups; gncomb-proven layout)
#pragma unroll 1
    for (int g = 0; g < 4; g++) {
        int grp = wid * 4 + g;
        size_t b450 = base + (size_t)grp * 450;
        int c0i = grp * 2;
        float v[15];
        float s = 0.f, s2 = 0.f;
#pragma unroll
        for (int kq = 0; kq < 15; kq++) {
            int i = kq * 32 + lane;
            float xv = 0.f;
            if (i < 450) {
                size_t idx = b450 + i;
                xv = y[idx];
                if (nk > 0) xv = fmaf(c0, k0[idx], xv);
                if (nk > 1) xv = fmaf(c1, k1[idx], xv);
                if (nk > 2) xv = fmaf(c2, k2[idx], xv);
                if (nk > 3) xv = fmaf(c3, k3[idx], xv);
                if (nk > 4) xv = fmaf(c4, k4[idx], xv);
                if (writeY) y[idx] = xv;
            }
            v[kq] = xv;
            s += xv; s2 = fmaf(xv, xv, s2);
        }
        s = warpSum(s); s2 = warpSum(s2);
        float mu = s * (1.f / 450.f);
        float inv = rsqrtf(s2 * (1.f / 450.f) - mu * mu + 1e-5f);
        float sc0 = inv * g1[c0i],     sh0 = bb1[c0i]     - mu * sc0;
        float sc1 = inv * g1[c0i + 1], sh1 = bb1[c0i + 1] - mu * sc1;
#pragma unroll
        for (int kq = 0; kq < 15; kq++) {
            int i = kq * 32 + lane;
            if (i < 450) {
                int ch = c0i + (i >= 225);
                int p = (i >= 225) ? i - 225 : i;
                float r = (i < 225) ? fmaf(v[kq], sc0, sh0) : fmaf(v[kq], sc1, sh1);
                r = fmaxf(r, 0.f);
                int rr = (p / 15 + 1) * 18 + (p % 15) + 1;
                hh[rr * 64 + ((((ch >> 3) ^ (rr & 7)) << 3) + (ch & 7))] = __float2half(r);
            }
        }
    }
    // conv_taps' leading __syncthreads orders halo writes before reads

    int row0 = lane >> 2;
    int colb = (lane & 3) * 2;
    bool v1ok = (row0 + 8) < 15;
    float* scv = (float*)(smem + MM_STAT) + 128;
    float* shv = scv + 64;

    float acc[2][8][4];

    // conv1 + GN2 -> halo (fp16, relu)
    conv_taps(smem, smBase + MM_HHI, smBase + MM_BHI, w1q, tid, wid, lane, acc);
    gn_stats_from_acc(smem, acc, b1, S1, t, g2, bb2, tid, wid, lane, row0, colb, v1ok);
#pragma unroll
    for (int mti = 0; mti < 2; mti++) {
        int mtile = wid + mti * 8;
        if (mtile >= 15) continue;
        int rbase = (mtile + 1) * 18 + 1;
#pragma unroll
        for (int nt = 0; nt < 8; nt++) {
            int co = nt * 8 + colb;
            float sc0 = scv[co], sh0 = shv[co];
            float sc1 = scv[co + 1], sh1 = shv[co + 1];
            int rr = rbase + row0;
            int swA = ((((co >> 3) ^ (rr & 7)) << 3) + (co & 7));
            int swB = (((((co + 1) >> 3) ^ (rr & 7)) << 3) + ((co + 1) & 7));
            hh[rr * 64 + swA] = __float2half(fmaxf(fmaf(acc[mti][nt][0], sc0, sh0), 0.f));
            hh[rr * 64 + swB] = __float2half(fmaxf(fmaf(acc[mti][nt][1], sc1, sh1), 0.f));
            if (v1ok) {
                int r2 = rr + 8;
                int swC = ((((co >> 3) ^ (r2 & 7)) << 3) + (co & 7));
                int swD = (((((co + 1) >> 3) ^ (r2 & 7)) << 3) + ((co + 1) & 7));
                hh[r2 * 64 + swC] = __float2half(fmaxf(fmaf(acc[mti][nt][2], sc0, sh0), 0.f));
                hh[r2 * 64 + swD] = __float2half(fmaxf(fmaf(acc[mti][nt][3], sc1, sh1), 0.f));
            }
        }
    }
    // conv_taps' leading __syncthreads orders GN2 halo writes before conv2 reads

    // conv2 + GN3 -> kout (no relu)
    conv_taps(smem, smBase + MM_HHI, smBase + MM_BHI, w2q, tid, wid, lane, acc);
    gn_stats_from_acc(smem, acc, b2, S2, t, g3, bb3, tid, wid, lane, row0, colb, v1ok);
#pragma unroll
    for (int mti = 0; mti < 2; mti++) {
        int mtile = wid + mti * 8;
        if (mtile >= 15) continue;
        int p0 = mtile * 15 + row0, p1 = p0 + 8;
#pragma unroll
        for (int nt = 0; nt < 8; nt++) {
            int co = nt * 8 + colb;
            float sc0 = scv[co], sh0 = shv[co];
            float sc1 = scv[co + 1], sh1 = shv[co + 1];
            float* oc0 = kout + base + (size_t)co * 225;
            float* oc1 = oc0 + 225;
            oc0[p0] = fmaf(acc[mti][nt][0], sc0, sh0);
            oc1[p0] = fmaf(acc[mti][nt][1], sc1, sh1);
            if (v1ok) {
                oc0[p1] = fmaf(acc[mti][nt][2], sc0, sh0);
                oc1[p1] = fmaf(acc[mti][nt][3], sc1, sh1);
            }
        }
    }
}

// ---------------- conv1: 1->64, 3x3, valid ----------------
__global__ void conv1_kernel(const float* __restrict__ x, float* __restrict__ out,
                             const float* __restrict__ w, const float* __restrict__ bias)
{
    __shared__ float sx[18][18];
    __shared__ float swt[64 * 9];
    __shared__ float sb[64];
    int b = blockIdx.y;
    int tileX = blockIdx.x & 3, tileY = blockIdx.x >> 2;
    int tx = threadIdx.x, ty = threadIdx.y;
    int tid = ty * 16 + tx;

    for (int s = tid; s < 576; s += 256) swt[s] = w[s];
    if (tid < 64) sb[tid] = bias[tid];

    const float* xb = x + (size_t)b * 64 * 64;
    int ox0 = tileX * 16, oy0 = tileY * 16;
    for (int s = tid; s < 18 * 18; s += 256) {
        int r = s / 18, c = s % 18;
        int iy = oy0 + r, ix = ox0 + c;
        sx[r][c] = (iy < 64 && ix < 64) ? xb[iy * 64 + ix] : 0.f;
    }
    __syncthreads();

    int ox = ox0 + tx, oy = oy0 + ty;
    if (ox >= 62 || oy >= 62) return;

    float v[9];
#pragma unroll
    for (int ky = 0; ky < 3; ky++)
#pragma unroll
        for (int kx = 0; kx < 3; kx++)
            v[ky * 3 + kx] = sx[ty + ky][tx + kx];

    float* ob = out + (size_t)b * 64 * 3844 + oy * 62 + ox;
#pragma unroll 4
    for (int co = 0; co < 64; co++) {
        float a = sb[co];
#pragma unroll
        for (int k = 0; k < 9; k++) a = fmaf(swt[co * 9 + k], v[k], a);
        ob[(size_t)co * 3844] = a;
    }
}

// ---------------- generic GroupNorm (big HW) ----------------
__global__ void gn_big_kernel(const float* __restrict__ in, float* __restrict__ out,
                              const float* __restrict__ gamma, const float* __restrict__ beta,
                              int HW, int relu)
{
    __shared__ float rs[8], rs2[8], stats[2];
    int bg = blockIdx.x;
    int c0 = (bg & 31) * 2;
    size_t base = (size_t)bg * 2 * HW;
    int n = 2 * HW;
    float s = 0.f, s2 = 0.f;
    for (int i = threadIdx.x; i < n; i += 256) {
        float v = in[base + i];
        s += v; s2 = fmaf(v, v, s2);
    }
    s = warpSum(s); s2 = warpSum(s2);
    int wi = threadIdx.x >> 5, lane = threadIdx.x & 31;
    if (lane == 0) { rs[wi] = s; rs2[wi] = s2; }
    __syncthreads();
    if (threadIdx.x == 0) {
        float a = 0.f, bb = 0.f;
#pragma unroll
        for (int i = 0; i < 8; i++) { a += rs[i]; bb += rs2[i]; }
        float mu = a / (float)n;
        stats[0] = mu;
        stats[1] = rsqrtf(bb / (float)n - mu * mu + 1e-5f);
    }
    __syncthreads();
    float mu = stats[0], inv = stats[1];
    float sc0 = inv * gamma[c0],     sh0 = beta[c0]     - mu * sc0;
    float sc1 = inv * gamma[c0 + 1], sh1 = beta[c0 + 1] - mu * sc1;
    for (int i = threadIdx.x; i < n; i += 256) {
        float v = in[base + i];
        float r = (i < HW) ? fmaf(v, sc0, sh0) : fmaf(v, sc1, sh1);
        if (relu) r = fmaxf(r, 0.f);
        out[base + i] = r;
    }
}

// ---------------- GroupNorm 15x15 (head only) ----------------
__global__ void gn8_kernel(const float* __restrict__ in, float* __restrict__ out,
                           const float* __restrict__ gamma, const float* __restrict__ beta,
                           int relu)
{
    int wid = threadIdx.x >> 5, lane = threadIdx.x & 31;
    int bg = blockIdx.x * 8 + wid;
    size_t base = (size_t)bg * 450;
    int c0 = (bg & 31) * 2;
    float v[15];
    float s = 0.f, s2 = 0.f;
#pragma unroll
    for (int k = 0; k < 15; k++) {
        int i = k * 32 + lane;
        float xv = (i < 450) ? in[base + i] : 0.f;
        v[k] = xv;
        s += xv; s2 = fmaf(xv, xv, s2);
    }
    s = warpSum(s); s2 = warpSum(s2);
    float mu = s * (1.f / 450.f);
    float inv = rsqrtf(s2 * (1.f / 450.f) - mu * mu + 1e-5f);
    float sc0 = inv * gamma[c0],     sh0 = beta[c0]     - mu * sc0;
    float sc1 = inv * gamma[c0 + 1], sh1 = beta[c0 + 1] - mu * sc1;
#pragma unroll
    for (int k = 0; k < 15; k++) {
        int i = k * 32 + lane;
        if (i < 450) {
            float r = (i < 225) ? fmaf(v[k], sc0, sh0) : fmaf(v[k], sc1, sh1);
            if (relu) r = fmaxf(r, 0.f);
            out[base + i] = r;
        }
    }
}

// ---------------- precompute S[co][p] ----------------
__global__ void precomp_s_kernel(const float* __restrict__ w, float* __restrict__ S)
{
    int co = blockIdx.x;
    int p = threadIdx.x;
    int y = p / 15, x = p % 15;
    float a = 0.f;
#pragma unroll
    for (int ky = 0; ky < 3; ky++) {
        int iy = y - 1 + ky;
        if ((unsigned)iy < 15u) {
#pragma unroll
            for (int kx = 0; kx < 3; kx++) {
                int ix = x - 1 + kx;
                if ((unsigned)ix < 15u) a += w[(size_t)co * 65 * 9 + ky * 3 + kx];
            }
        }
    }
    S[co * 225 + p] = a;
}

// ---------------- precompute swizzled fp16 weights per tap (3x3) ----------------
__global__ void precomp_w_kernel(const float* __restrict__ w, __half* __restrict__ hi)
{
    int tap = blockIdx.x;
    for (int s = threadIdx.x; s < 4096; s += 256) {
        int co = s >> 6, ci = s & 63;
        float v = w[((size_t)co * 65 + ci + 1) * 9 + tap];
        int pos = tap * 4096 + co * 64 + ((((ci >> 3) ^ (co & 7)) << 3) + (ci & 7));
        hi[pos] = __float2half(v);
    }
}

// ---------------- precompute swizzled fp16 weights per tap (4x4) ----------------
__global__ void precomp_w4_kernel(const float* __restrict__ w, __half* __restrict__ hi)
{
    int tap = blockIdx.x;
    for (int s = threadIdx.x; s < 4096; s += 256) {
        int co = s >> 6, ci = s & 63;
        float v = w[(((size_t)co * 64) + ci) * 16 + tap];
        int pos = tap * 4096 + co * 64 + ((((ci >> 3) ^ (co & 7)) << 3) + (ci & 7));
        hi[pos] = __float2half(v);
    }
}

// ---------------- downsample conv 4x4 stride2 pad1 via fp16 mma ----------------
__global__ void __launch_bounds__(256, 2)
conv4_mma(const float* __restrict__ in, float* __restrict__ out,
          const __half* __restrict__ wq, const float* __restrict__ bias,
          int Hin, int Hout)
{
    extern __shared__ __align__(128) char smem[];
    uint32_t smBase = smem_u32(smem);
    const uint32_t HA = smBase;
    const uint32_t BA = smBase + C4_W;

    int tid = threadIdx.x;
    int wid = tid >> 5, lane = tid & 31;
    int b = blockIdx.z;
    int ox0 = blockIdx.x * 16, oy0 = blockIdx.y * 8;
    int iy0 = 2 * oy0 - 1, ix0 = 2 * ox0 - 1;

    {
        uint4 z = make_uint4(0u, 0u, 0u, 0u);
        uint4* h4 = (uint4*)smem;
        for (int i = tid; i < 4896; i += 256) h4[i] = z;
    }
    __syncthreads();
    {
        __half* hh = (__half*)smem;
        const float* inb = in + ((size_t)b * 64) * Hin * Hin;
        for (int s = tid; s < 64 * 612; s += 256) {
            int ci = s / 612, rr = s % 612;
            int ly = rr / 34, lx = rr % 34;
            int iy = iy0 + ly, ix = ix0 + lx;
            if ((unsigned)iy < (unsigned)Hin && (unsigned)ix < (unsigned)Hin) {
                float v = inb[(size_t)ci * Hin * Hin + iy * Hin + ix];
                int off = rr * 64 + ((((ci >> 3) ^ (rr & 7)) << 3) + (ci & 7));
                hh[off] = __float2half(v);
            }
        }
    }

    float acc[8][4];
#pragma unroll
    for (int n = 0; n < 8; n++)
#pragma unroll
        for (int v = 0; v < 4; v++) acc[n][v] = 0.f;

    for (int tap = 0; tap < 16; tap++) {
        __syncthreads();
        {
            const uint4* gh = (const uint4*)(wq + tap * 4096);
            uint4* sh = (uint4*)(smem + C4_W);
            for (int i = tid; i < 512; i += 256) sh[i] = gh[i];
        }
        __syncthreads();

        int ky = tap >> 2, kx = tap & 3;
        for (int kt = 0; kt < 4; kt++) {
            uint32_t bh[8][2];
            int nrow = lane & 7;
            int bphys = ((kt * 2 + ((lane >> 3) & 1)) ^ nrow) * 16;
#pragma unroll
            for (int nt = 0; nt < 8; nt++)
                ldsm2(bh[nt], BA + (nt * 8 + nrow) * 128 + bphys);

            int r = (2 * wid + ky) * 34 + 2 * (lane & 15) + kx;
            int aphys = ((kt * 2 + (lane >> 4)) ^ (r & 7)) * 16;
            uint32_t ah[4];
            ldsm4(ah, HA + r * 128 + aphys);
#pragma unroll
            for (int nt = 0; nt < 8; nt++)
                mma_fp16(acc[nt], ah, bh[nt]);
        }
    }

    int oy = oy0 + wid;
    if (oy < Hout) {
        int row0 = lane >> 2;
        int colb = (lane & 3) * 2;
        int oxa = ox0 + row0, oxb = ox0 + row0 + 8;
        int HW = Hout * Hout;
        float* ob = out + ((size_t)b * 64) * HW + oy * Hout;
#pragma unroll
        for (int nt = 0; nt < 8; nt++) {
            int co = nt * 8 + colb;
            float bv0 = __ldg(&bias[co]), bv1 = __ldg(&bias[co + 1]);
            if (oxa < Hout) {
                ob[(size_t)co * HW + oxa] = acc[nt][0] + bv0;
                ob[(size_t)(co + 1) * HW + oxa] = acc[nt][1] + bv1;
            }
            if (oxb < Hout) {
                ob[(size_t)co * HW + oxb] = acc[nt][2] + bv0;
                ob[(size_t)(co + 1) * HW + oxb] = acc[nt][3] + bv1;
            }
        }
    }
}

// ---------------- final combine ----------------
__global__ void combine_kernel(const float4* __restrict__ y, float4* __restrict__ dst,
                               const float4* __restrict__ p0, const float4* __restrict__ p1,
                               const float4* __restrict__ p2, const float4* __restrict__ p3,
                               const float4* __restrict__ p4,
                               float c0, float c1, float c2, float c3, float c4)
{
    int i = blockIdx.x * 256 + threadIdx.x;
    float4 a = y[i];
    float4 t;
    t = p0[i]; a.x = fmaf(c0, t.x, a.x); a.y = fmaf(c0, t.y, a.y); a.z = fmaf(c0, t.z, a.z); a.w = fmaf(c0, t.w, a.w);
    t = p1[i]; a.x = fmaf(c1, t.x, a.x); a.y = fmaf(c1, t.y, a.y); a.z = fmaf(c1, t.z, a.z); a.w = fmaf(c1, t.w, a.w);
    t = p2[i]; a.x = fmaf(c2, t.x, a.x); a.y = fmaf(c2, t.y, a.y); a.z = fmaf(c2, t.z, a.z); a.w = fmaf(c2, t.w, a.w);
    t = p3[i]; a.x = fmaf(c3, t.x, a.x); a.y = fmaf(c3, t.y, a.y); a.z = fmaf(c3, t.z, a.z); a.w = fmaf(c3, t.w, a.w);
    t = p4[i]; a.x = fmaf(c4, t.x, a.x); a.y = fmaf(c4, t.y, a.y); a.z = fmaf(c4, t.z, a.z); a.w = fmaf(c4, t.w, a.w);
    dst[i] = a;
}

// ---------------- global mean pool ----------------
__global__ void pool_kernel(const float* __restrict__ in, float* __restrict__ out)
{
    int gw = (blockIdx.x * 256 + threadIdx.x) >> 5;
    int lane = threadIdx.x & 31;
    const float* p = in + (size_t)gw * 225;
    float s = 0.f;
    for (int i = lane; i < 225; i += 32) s += p[i];
    s = warpSum(s);
    if (lane == 0) out[gw] = s * (1.f / 225.f);
}

// ---------------- FC 64->10 ----------------
__global__ void fc_kernel(const float* __restrict__ pool, const float* __restrict__ w,
                          const float* __restrict__ bias, float* __restrict__ out)
{
    __shared__ float sp[64];
    int b = blockIdx.x;
    sp[threadIdx.x] = pool[b * 64 + threadIdx.x];
    __syncthreads();
    if (threadIdx.x < 10) {
        float a = bias[threadIdx.x];
#pragma unroll
        for (int c = 0; c < 64; c++) a = fmaf(sp[c], __ldg(&w[threadIdx.x * 64 + c]), a);
        out[b * 10 + threadIdx.x] = a;
    }
}

// ---------------- launch ----------------
extern "C" void kernel_launch(void* const* d_in, const int* in_sizes, int n_in,
                              void* d_out, int out_size)
{
    const float* x        = (const float*)d_in[0];
    const float* conv1_w  = (const float*)d_in[1];
    const float* conv1_b  = (const float*)d_in[2];
    const float* gn1_g    = (const float*)d_in[3];
    const float* gn1_b    = (const float*)d_in[4];
    const float* conv2_w  = (const float*)d_in[5];
    const float* conv2_b  = (const float*)d_in[6];
    const float* gn2_g    = (const float*)d_in[7];
    const float* gn2_b    = (const float*)d_in[8];
    const float* conv3_w  = (const float*)d_in[9];
    const float* conv3_b  = (const float*)d_in[10];
    const float* f_gn1_g  = (const float*)d_in[11];
    const float* f_gn1_b  = (const float*)d_in[12];
    const float* f_conv1_w= (const float*)d_in[13];
    const float* f_conv1_b= (const float*)d_in[14];
    const float* f_gn2_g  = (const float*)d_in[15];
    const float* f_gn2_b  = (const float*)d_in[16];
    const float* f_conv2_w= (const float*)d_in[17];
    const float* f_conv2_b= (const float*)d_in[18];
    const float* f_gn3_g  = (const float*)d_in[19];
    const float* f_gn3_b  = (const float*)d_in[20];
    const float* out_gn_g = (const float*)d_in[21];
    const float* out_gn_b = (const float*)d_in[22];
    const float* fc_w     = (const float*)d_in[23];
    const float* fc_b     = (const float*)d_in[24];
    float* out = (float*)d_out;

    float *h1, *h2, *y, *t0b, *kbase, *S1, *S2, *pool;
    __half *w1q, *w2q, *w4a, *w4b;
    cudaGetSymbolAddress((void**)&h1, g_h1);
    cudaGetSymbolAddress((void**)&h2, g_h2);
    cudaGetSymbolAddress((void**)&y, g_y);
    cudaGetSymbolAddress((void**)&t0b, g_t0);
    cudaGetSymbolAddress((void**)&kbase, g_k);
    cudaGetSymbolAddress((void**)&S1, g_S1);
    cudaGetSymbolAddress((void**)&S2, g_S2);
    cudaGetSymbolAddress((void**)&pool, g_pool);
    cudaGetSymbolAddress((void**)&w1q, g_w1);
    cudaGetSymbolAddress((void**)&w2q, g_w2);
    cudaGetSymbolAddress((void**)&w4a, g_w4a);
    cudaGetSymbolAddress((void**)&w4b, g_w4b);
    float* kk[6];
    for (int i = 0; i < 6; i++) kk[i] = kbase + (size_t)i * NY;

    cudaFuncSetAttribute(feval_fused, cudaFuncAttributeMaxDynamicSharedMemorySize, MM_SMEM_BYTES);
    cudaFuncSetAttribute(conv4_mma, cudaFuncAttributeMaxDynamicSharedMemorySize, C4_SMEM_BYTES);

    // ---- downsampling ----
    conv1_kernel<<<dim3(16, BATCH), dim3(16, 16)>>>(x, h1, conv1_w, conv1_b);
    gn_big_kernel<<<BATCH * 32, 256>>>(h1, h1, gn1_g, gn1_b, 62 * 62, 1);
    precomp_w4_kernel<<<16, 256>>>(conv2_w, w4a);
    precomp_w4_kernel<<<16, 256>>>(conv3_w, w4b);
    conv4_mma<<<dim3(2, 4, BATCH), 256, C4_SMEM_BYTES>>>(h1, h2, w4a, conv2_b, 62, 31);
    gn_big_kernel<<<BATCH * 32, 256>>>(h2, h2, gn2_g, gn2_b, 31 * 31, 1);
    conv4_mma<<<dim3(1, 2, BATCH), 256, C4_SMEM_BYTES>>>(h2, y, w4b, conv3_b, 31, 15);

    precomp_s_kernel<<<64, 225>>>(f_conv1_w, S1);
    precomp_s_kernel<<<64, 225>>>(f_conv2_w, S2);
    precomp_w_kernel<<<9, 256>>>(f_conv1_w, w1q);
    precomp_w_kernel<<<9, 256>>>(f_conv2_w, w2q);

    // feval = ONE kernel
    auto fev = [&](float t, const float* p0, const float* p1, const float* p2,
                   const float* p3, const float* p4,
                   double c0, double c1, double c2, double c3, double c4,
                   int nk, int writeY, float* kout) {
        feval_fused<<<BATCH, 256, MM_SMEM_BYTES>>>(
            y, p0 ? p0 : y, p1 ? p1 : y, p2 ? p2 : y, p3 ? p3 : y, p4 ? p4 : y,
            (float)c0, (float)c1, (float)c2, (float)c3, (float)c4, nk, writeY,
            f_gn1_g, f_gn1_b, w1q, f_conv1_b, S1,
            f_gn2_g, f_gn2_b, w2q, f_conv2_b, S2,
            f_gn3_g, f_gn3_b, t, kout);
    };

    const double hs = 1.0 / 8.0;
    const double bf0 = hs * (35.0 / 384.0),  bf2 = hs * (500.0 / 1113.0);
    const double bf3 = hs * (125.0 / 192.0), bf4 = hs * (-2187.0 / 6784.0);
    const double bf5 = hs * (11.0 / 84.0);

    for (int st = 0; st < 8; st++) {
        double T0 = st * hs;
        if (st == 0)
            fev((float)T0, 0, 0, 0, 0, 0, 0, 0, 0, 0, 0, 0, 0, kk[0]);
        else
            fev((float)T0, kk[0], kk[2], kk[3], kk[4], kk[5],
                bf0, bf2, bf3, bf4, bf5, 5, 1, kk[0]);
        fev((float)(T0 + hs / 5.0), kk[0], 0, 0, 0, 0,
            hs * (1.0 / 5.0), 0, 0, 0, 0, 1, 0, kk[1]);
        fev((float)(T0 + 0.3 * hs), kk[0], kk[1], 0, 0, 0,
            hs * (3.0 / 40.0), hs * (9.0 / 40.0), 0, 0, 0, 2, 0, kk[2]);
        fev((float)(T0 + 0.8 * hs), kk[0], kk[1], kk[2], 0, 0,
            hs * (44.0 / 45.0), hs * (-56.0 / 15.0), hs * (32.0 / 9.0), 0, 0, 3, 0, kk[3]);
        fev((float)(T0 + (8.0 / 9.0) * hs), kk[0], kk[1], kk[2], kk[3], 0,
            hs * (19372.0 / 6561.0), hs * (-25360.0 / 2187.0),
            hs * (64448.0 / 6561.0), hs * (-212.0 / 729.0), 0, 4, 0, kk[4]);
        fev((float)(T0 + hs), kk[0], kk[1], kk[2], kk[3], kk[4],
            hs * (9017.0 / 3168.0), hs * (-355.0 / 33.0), hs * (46732.0 / 5247.0),
            hs * (49.0 / 176.0), hs * (-5103.0 / 18656.0), 5, 0, kk[5]);
    }
    // final y update for step 7
    combine_kernel<<<3600, 256>>>((const float4*)y, (float4*)y,
        (const float4*)kk[0], (const float4*)kk[2], (const float4*)kk[3],
        (const float4*)kk[4], (const float4*)kk[5],
        (float)bf0, (float)bf2, (float)bf3, (float)bf4, (float)bf5);

    // ---- head ----
    gn8_kernel<<<1024, 256>>>(y, t0b, out_gn_g, out_gn_b, 1);
    pool_kernel<<<2048, 256>>>(t0b, pool);
    fc_kernel<<<BATCH, 64>>>(pool, fc_w, fc_b, out);
}